// round 11
// baseline (speedup 1.0000x reference)
#include <cuda_runtime.h>
#include <cuda_bf16.h>
#include <cfloat>
#include <cstdint>

// Problem shape (fixed): B=8, N=2048, D=256
#define BATCH 8
#define NDIM  2048
#define DDIM  256

#define TILE 128
#define NT   (NDIM / TILE)               // 16
#define NPAIR ((NT * (NT + 1)) / 2)      // 136
#define TOTAL_PAIRS (NPAIR * BATCH)      // 1088
#define NCTA 296                         // 2 CTAs per SM
#define NCHUNK 4096                      // softmax chunks (4 rows each)

// ---------------------------------------------------------------------------
// Device scratch (allocation-free)
// ---------------------------------------------------------------------------
__device__ float g_energy[(size_t)BATCH * NDIM * NDIM];            // 134 MB
__device__ uint4 g_hhi[524288];   // h hi bf16
__device__ uint4 g_hlo[524288];   // h lo bf16
__device__ int   g_cnt[BATCH * NT];  // per (batch, tile-row) tiles done (goal 16)

// ---------------------------------------------------------------------------
// Kernel 0: split h -> hi/lo bf16; block 0 zeroes counters (every replay).
// ---------------------------------------------------------------------------
__global__ void __launch_bounds__(256)
convert_kernel(const float4* __restrict__ h4)
{
    if (blockIdx.x == 0 && threadIdx.x < BATCH * NT)
        g_cnt[threadIdx.x] = 0;

    const int base = blockIdx.x * 512 + threadIdx.x;
    #pragma unroll
    for (int i = 0; i < 2; ++i) {
        const int f = base + i * 256;
        const float4 v = h4[f];
        __nv_bfloat16 hx = __float2bfloat16_rn(v.x);
        __nv_bfloat16 hy = __float2bfloat16_rn(v.y);
        __nv_bfloat16 hz = __float2bfloat16_rn(v.z);
        __nv_bfloat16 hw = __float2bfloat16_rn(v.w);
        float lx = v.x - __bfloat162float(hx);
        float ly = v.y - __bfloat162float(hy);
        float lz = v.z - __bfloat162float(hz);
        float lw = v.w - __bfloat162float(hw);
        __nv_bfloat162 hi01 = __nv_bfloat162(hx, hy);
        __nv_bfloat162 hi23 = __nv_bfloat162(hz, hw);
        __nv_bfloat162 lo01 = __floats2bfloat162_rn(lx, ly);
        __nv_bfloat162 lo23 = __floats2bfloat162_rn(lz, lw);
        uint2 uh, ul;
        uh.x = *reinterpret_cast<uint32_t*>(&hi01);
        uh.y = *reinterpret_cast<uint32_t*>(&hi23);
        ul.x = *reinterpret_cast<uint32_t*>(&lo01);
        ul.y = *reinterpret_cast<uint32_t*>(&lo23);
        reinterpret_cast<uint2*>(g_hhi)[f] = uh;
        reinterpret_cast<uint2*>(g_hlo)[f] = ul;
    }
}

// ---------------------------------------------------------------------------
// mma.sync / ldmatrix / cp.async helpers
// ---------------------------------------------------------------------------
__device__ __forceinline__ uint32_t smem_u32(const void* p) {
    uint32_t a;
    asm("{ .reg .u64 t; cvta.to.shared.u64 t, %1; cvt.u32.u64 %0, t; }"
        : "=r"(a) : "l"(p));
    return a;
}

__device__ __forceinline__ void ldsm_x4(uint32_t* r, uint32_t addr) {
    asm volatile("ldmatrix.sync.aligned.m8n8.x4.shared.b16 {%0,%1,%2,%3}, [%4];"
                 : "=r"(r[0]), "=r"(r[1]), "=r"(r[2]), "=r"(r[3]) : "r"(addr));
}

__device__ __forceinline__ void mma16816(float* d, const uint32_t* a,
                                         const uint32_t* b) {
    asm volatile("mma.sync.aligned.m16n8k16.row.col.f32.bf16.bf16.f32 "
                 "{%0,%1,%2,%3}, {%4,%5,%6,%7}, {%8,%9}, {%0,%1,%2,%3};"
                 : "+f"(d[0]), "+f"(d[1]), "+f"(d[2]), "+f"(d[3])
                 : "r"(a[0]), "r"(a[1]), "r"(a[2]), "r"(a[3]),
                   "r"(b[0]), "r"(b[1]));
}

__device__ __forceinline__ void cp_async16(uint32_t smem_dst, const void* gptr) {
    asm volatile("cp.async.cg.shared.global [%0], [%1], 16;\n"
                 :: "r"(smem_dst), "l"(__cvta_generic_to_global(gptr))
                 : "memory");
}
#define CP_COMMIT() asm volatile("cp.async.commit_group;\n" ::: "memory")
#define CP_WAIT(n)  asm volatile("cp.async.wait_group %0;\n" :: "n"(n) : "memory")

__device__ __forceinline__ uint32_t swz(int row, int kc) {
    return (uint32_t)(row * 64 + ((kc ^ ((row >> 1) & 3)) << 4));
}

#define STAGE_BYTES 32768
#define ARR_BYTES   8192
#define FLAG_OFF    (3 * STAGE_BYTES)        // 98304 (int flag)
#define RED_OFF     (FLAG_OFF + 16)          // 32 floats reduction scratch
#define FUSED_SMEM  (RED_OFF + 128)          // 98448; x2 CTAs = 196,896 B/SM

// pair index m (row-block-major: for rb { for b { for tj } }) -> (b, ti, tj)
__device__ __forceinline__ void decode_pair(int m, int& b, int& ti, int& tj)
{
    int rem = m, rb = 0;
    while (rem >= BATCH * (NT - rb)) { rem -= BATCH * (NT - rb); ++rb; }
    const int width = NT - rb;
    b  = rem / width;
    ti = rb;
    tj = rb + (rem % width);
}

__device__ __forceinline__ void load_stage(uint32_t sm_stage, int a_row0,
                                           int b_row0, int c, int tid,
                                           int batch4)
{
    #pragma unroll
    for (int i = 0; i < 8; ++i) {
        const int id  = tid + i * 256;
        const int arr = id >> 9;            // 0=Ahi 1=Alo 2=Bhi 3=Blo
        const int cid = id & 511;
        const int row = cid >> 2;
        const int ch  = cid & 3;
        const uint32_t dst = sm_stage + arr * ARR_BYTES + swz(row, ch);
        const int grow = ((arr < 2) ? a_row0 : b_row0) + row;
        const uint4* src = ((arr & 1) ? g_hlo : g_hhi)
                           + batch4 + grow * 32 + c * 4 + ch;
        cp_async16(dst, src);
    }
}

// ---------------------------------------------------------------------------
// One syrk pair: R10 mainloop (3-stage ring, 1 barrier/chunk) + epilogue +
// fenced counter publish.
// ---------------------------------------------------------------------------
__device__ void syrk_pair(char* smc, uint32_t smem_base, int m)
{
    const int tid  = threadIdx.x;
    const int wid  = tid >> 5;
    const int lane = tid & 31;

    int b, ti, tj;
    decode_pair(m, b, ti, tj);
    const int a_base = ti * TILE;
    const int b_base = tj * TILE;
    const int batch4 = b * 65536;

    const int wm = (wid & 3) * 32;
    const int wn = (wid >> 2) * 64;

    const int r8   = lane & 7;
    const int a_dr = (lane & 8);
    const int a_dk = (lane >> 4);
    const int b_dr = (lane & 16) >> 1;
    const int b_dk = (lane >> 3) & 1;

    float acc[2][8][4];
    #pragma unroll
    for (int mt = 0; mt < 2; ++mt)
        #pragma unroll
        for (int nt = 0; nt < 8; ++nt)
            #pragma unroll
            for (int q = 0; q < 4; ++q)
                acc[mt][nt][q] = 0.0f;

    load_stage(smem_base,               a_base, b_base, 0, tid, batch4);
    CP_COMMIT();
    load_stage(smem_base + STAGE_BYTES, a_base, b_base, 1, tid, batch4);
    CP_COMMIT();

    #pragma unroll 1
    for (int c = 0; c < 8; ++c) {
        if (c < 7) { CP_WAIT(1); } else { CP_WAIT(0); }
        __syncthreads();

        const uint32_t sb  = smem_base + (uint32_t)(c % 3) * STAGE_BYTES;
        const uint32_t sAh = sb;
        const uint32_t sAl = sb + ARR_BYTES;
        const uint32_t sBh = sb + 2 * ARR_BYTES;
        const uint32_t sBl = sb + 3 * ARR_BYTES;

        if (c + 2 < 8) {
            load_stage(smem_base + (uint32_t)((c + 2) % 3) * STAGE_BYTES,
                       a_base, b_base, c + 2, tid, batch4);
        }
        CP_COMMIT();

        #pragma unroll
        for (int ks = 0; ks < 2; ++ks) {
            uint32_t ahi[2][4], alo[2][4], bf[4][4];

            #pragma unroll
            for (int mt = 0; mt < 2; ++mt) {
                const int row = wm + mt * 16 + a_dr + r8;
                const int kc  = 2 * ks + a_dk;
                const uint32_t off = swz(row, kc);
                ldsm_x4(ahi[mt], sAh + off);
                ldsm_x4(alo[mt], sAl + off);
            }
            #pragma unroll
            for (int np = 0; np < 4; ++np) {
                const int row = wn + np * 16 + b_dr + r8;
                const int kc  = 2 * ks + b_dk;
                ldsm_x4(bf[np], sBh + swz(row, kc));
            }
            #pragma unroll
            for (int mt = 0; mt < 2; ++mt)
                #pragma unroll
                for (int np = 0; np < 4; ++np) {
                    mma16816(acc[mt][2 * np],     ahi[mt], &bf[np][0]);
                    mma16816(acc[mt][2 * np + 1], ahi[mt], &bf[np][2]);
                    mma16816(acc[mt][2 * np],     alo[mt], &bf[np][0]);
                    mma16816(acc[mt][2 * np + 1], alo[mt], &bf[np][2]);
                }
            #pragma unroll
            for (int np = 0; np < 4; ++np) {
                const int row = wn + np * 16 + b_dr + r8;
                const int kc  = 2 * ks + b_dk;
                ldsm_x4(bf[np], sBl + swz(row, kc));
            }
            #pragma unroll
            for (int mt = 0; mt < 2; ++mt)
                #pragma unroll
                for (int np = 0; np < 4; ++np) {
                    mma16816(acc[mt][2 * np],     ahi[mt], &bf[np][0]);
                    mma16816(acc[mt][2 * np + 1], ahi[mt], &bf[np][2]);
                }
        }
    }

    __syncthreads();

    float* sD = reinterpret_cast<float*>(smc);
    {
        const int rq = lane >> 2;
        const int cq = (lane & 3) * 2;
        #pragma unroll
        for (int mt = 0; mt < 2; ++mt) {
            const int r0 = wm + mt * 16 + rq;
            #pragma unroll
            for (int nt = 0; nt < 8; ++nt) {
                const int cc = wn + nt * 8 + cq;
                sD[r0 * 129 + cc]           = acc[mt][nt][0];
                sD[r0 * 129 + cc + 1]       = acc[mt][nt][1];
                sD[(r0 + 8) * 129 + cc]     = acc[mt][nt][2];
                sD[(r0 + 8) * 129 + cc + 1] = acc[mt][nt][3];
            }
        }
    }
    __syncthreads();

    float* eb = g_energy + (size_t)b * NDIM * NDIM;

    #pragma unroll 4
    for (int i = 0; i < 16; ++i) {
        const int idx = tid + i * 256;
        const int r  = idx >> 5;
        const int c4 = (idx & 31) * 4;
        float4 v = make_float4(sD[r * 129 + c4 + 0], sD[r * 129 + c4 + 1],
                               sD[r * 129 + c4 + 2], sD[r * 129 + c4 + 3]);
        __stcs(reinterpret_cast<float4*>(
            &eb[(size_t)(a_base + r) * NDIM + b_base + c4]), v);
    }

    if (ti != tj) {
        #pragma unroll 4
        for (int i = 0; i < 16; ++i) {
            const int idx = tid + i * 256;
            const int r2 = idx >> 5;
            const int c4 = (idx & 31) * 4;
            float4 v = make_float4(sD[(c4 + 0) * 129 + r2],
                                   sD[(c4 + 1) * 129 + r2],
                                   sD[(c4 + 2) * 129 + r2],
                                   sD[(c4 + 3) * 129 + r2]);
            __stcs(reinterpret_cast<float4*>(
                &eb[(size_t)(b_base + r2) * NDIM + a_base + c4]), v);
        }
    }

    // publish: release pattern (fence per thread, barrier, single atomic)
    __threadfence();
    __syncthreads();
    if (tid == 0) {
        atomicAdd(&g_cnt[b * NT + ti], 1);
        if (ti != tj) atomicAdd(&g_cnt[b * NT + tj], 1);
    }
    __syncthreads();
}

// ---------------------------------------------------------------------------
// softmax chunk machinery (4 rows / chunk, rb-major consumption order)
// ---------------------------------------------------------------------------
__device__ __forceinline__ void red4_max(float mv[4], float* red,
                                         int wid, int lid)
{
    #pragma unroll
    for (int r = 0; r < 4; ++r)
        #pragma unroll
        for (int o = 16; o > 0; o >>= 1)
            mv[r] = fmaxf(mv[r], __shfl_xor_sync(0xFFFFFFFFu, mv[r], o));
    if (lid == 0) {
        #pragma unroll
        for (int r = 0; r < 4; ++r) red[wid * 4 + r] = mv[r];
    }
    __syncthreads();
    #pragma unroll
    for (int r = 0; r < 4; ++r) {
        float v = red[r];
        #pragma unroll
        for (int w = 1; w < 8; ++w) v = fmaxf(v, red[w * 4 + r]);
        mv[r] = v;
    }
    __syncthreads();
}

__device__ __forceinline__ void red4_sum(float sv[4], float* red,
                                         int wid, int lid)
{
    #pragma unroll
    for (int r = 0; r < 4; ++r)
        #pragma unroll
        for (int o = 16; o > 0; o >>= 1)
            sv[r] += __shfl_xor_sync(0xFFFFFFFFu, sv[r], o);
    if (lid == 0) {
        #pragma unroll
        for (int r = 0; r < 4; ++r) red[wid * 4 + r] = sv[r];
    }
    __syncthreads();
    #pragma unroll
    for (int r = 0; r < 4; ++r) {
        float v = red[r];
        #pragma unroll
        for (int w = 1; w < 8; ++w) v += red[w * 4 + r];
        sv[r] = v;
    }
    __syncthreads();
}

__device__ void do_chunk(char* smc, int cs,
                         const float* __restrict__ adj,
                         float* __restrict__ out)
{
    float* red = reinterpret_cast<float*>(smc + RED_OFF);
    const int tid = threadIdx.x;
    const int wid = tid >> 5;
    const int lid = tid & 31;

    const int s0  = cs * 4;
    const int rb  = s0 >> 10;
    const int rem = s0 & 1023;
    const int b   = rem >> 7;
    const int r0  = rem & 127;
    const size_t row0 = (size_t)b * NDIM + (size_t)rb * 128 + r0;

    float4 ev[4][2], av[4][2];
    #pragma unroll
    for (int r = 0; r < 4; ++r) {
        const float4* e4 = reinterpret_cast<const float4*>(
            g_energy + (row0 + r) * NDIM);
        const float4* a4 = reinterpret_cast<const float4*>(
            adj + (row0 + r) * NDIM);
        ev[r][0] = __ldcs(e4 + tid);
        ev[r][1] = __ldcs(e4 + tid + 256);
        av[r][0] = __ldcs(a4 + tid);
        av[r][1] = __ldcs(a4 + tid + 256);
    }

    float m1[4];
    #pragma unroll
    for (int r = 0; r < 4; ++r)
        m1[r] = fmaxf(fmaxf(fmaxf(ev[r][0].x, ev[r][0].y),
                            fmaxf(ev[r][0].z, ev[r][0].w)),
                      fmaxf(fmaxf(ev[r][1].x, ev[r][1].y),
                            fmaxf(ev[r][1].z, ev[r][1].w)));
    red4_max(m1, red, wid, lid);

    float t[4][8], m2[4];
    #pragma unroll
    for (int r = 0; r < 4; ++r) {
        t[r][0] = (m1[r] - ev[r][0].x) * av[r][0].x;
        t[r][1] = (m1[r] - ev[r][0].y) * av[r][0].y;
        t[r][2] = (m1[r] - ev[r][0].z) * av[r][0].z;
        t[r][3] = (m1[r] - ev[r][0].w) * av[r][0].w;
        t[r][4] = (m1[r] - ev[r][1].x) * av[r][1].x;
        t[r][5] = (m1[r] - ev[r][1].y) * av[r][1].y;
        t[r][6] = (m1[r] - ev[r][1].z) * av[r][1].z;
        t[r][7] = (m1[r] - ev[r][1].w) * av[r][1].w;
        float mm = t[r][0];
        #pragma unroll
        for (int i = 1; i < 8; ++i) mm = fmaxf(mm, t[r][i]);
        m2[r] = mm;
    }
    red4_max(m2, red, wid, lid);

    float sv[4];
    #pragma unroll
    for (int r = 0; r < 4; ++r) {
        float s = 0.0f;
        #pragma unroll
        for (int i = 0; i < 8; ++i) { t[r][i] = __expf(t[r][i] - m2[r]); s += t[r][i]; }
        sv[r] = s;
    }
    red4_sum(sv, red, wid, lid);

    #pragma unroll
    for (int r = 0; r < 4; ++r) {
        const float inv = 1.0f / sv[r];
        float4* o4 = reinterpret_cast<float4*>(out + (row0 + r) * NDIM);
        __stcs(o4 + tid, make_float4(t[r][0] * inv, t[r][1] * inv,
                                     t[r][2] * inv, t[r][3] * inv));
        __stcs(o4 + tid + 256, make_float4(t[r][4] * inv, t[r][5] * inv,
                                           t[r][6] * inv, t[r][7] * inv));
    }
}

// Consume assigned chunks starting at *cs. blocking=false: stop at first
// not-ready (or cap). blocking=true: wait for each until all consumed.
__device__ void consume(char* smc, int& cs, int cap, bool blocking,
                        const float* __restrict__ adj,
                        float* __restrict__ out)
{
    int* flag = reinterpret_cast<int*>(smc + FLAG_OFF);
    const int tid = threadIdx.x;
    int done = 0;

    while (cs < NCHUNK && (blocking || done < cap)) {
        const int s0 = cs * 4;
        const int rb = s0 >> 10;
        const int b  = (s0 & 1023) >> 7;
        const int ci = b * NT + rb;

        if (tid == 0) {
            if (blocking) {
                while (*(volatile int*)&g_cnt[ci] < NT) __nanosleep(128);
                *flag = 1;
            } else {
                *flag = (*(volatile int*)&g_cnt[ci] >= NT) ? 1 : 0;
            }
        }
        __syncthreads();
        const int ok = *flag;
        // do_chunk's internal barriers separate this read from the next write
        if (!ok) break;
        __threadfence();    // acquire: order energy reads after flag
        do_chunk(smc, cs, adj, out);
        cs += NCTA;
        ++done;
    }
}

// ---------------------------------------------------------------------------
// Fused persistent kernel: every CTA produces (syrk pairs) and consumes
// (softmax chunks) — time-interleaved, 2 CTAs/SM throughout.
// ---------------------------------------------------------------------------
__global__ void __launch_bounds__(256, 2)
fused_kernel(const float* __restrict__ adj, float* __restrict__ out)
{
    extern __shared__ char smc[];
    const uint32_t smem_base = smem_u32(smc);
    const int bid = blockIdx.x;

    int cs = bid;   // next assigned softmax chunk

    #pragma unroll 1
    for (int m = bid; m < TOTAL_PAIRS; m += NCTA) {
        syrk_pair(smc, smem_base, m);
        consume(smc, cs, 6, false, adj, out);   // opportunistic, capped
    }
    consume(smc, cs, 0, true, adj, out);        // drain (blocking)
}

// ---------------------------------------------------------------------------
extern "C" void kernel_launch(void* const* d_in, const int* in_sizes, int n_in,
                              void* d_out, int out_size)
{
    const float* h   = (const float*)d_in[0];   // [8, 2048, 256]
    const float* adj = (const float*)d_in[1];   // [8, 2048, 2048]
    float*       out = (float*)d_out;           // [8, 2048, 2048]
    (void)in_sizes; (void)n_in; (void)out_size;

    cudaFuncSetAttribute(fused_kernel,
                         cudaFuncAttributeMaxDynamicSharedMemorySize,
                         FUSED_SMEM);

    convert_kernel<<<2048, 256>>>(reinterpret_cast<const float4*>(h));

    fused_kernel<<<NCTA, 256, FUSED_SMEM>>>(adj, out);
}

// round 12
// speedup vs baseline: 1.2127x; 1.2127x over previous
#include <cuda_runtime.h>
#include <cuda_bf16.h>
#include <cfloat>
#include <cstdint>

// Problem shape (fixed): B=8, N=2048, D=256
#define BATCH 8
#define NDIM  2048
#define DDIM  256

#define TILE 128
#define NT   (NDIM / TILE)               // 16
#define NPAIR ((NT * (NT + 1)) / 2)      // 136 upper-tri tile pairs

// ---------------------------------------------------------------------------
// Device scratch (allocation-free)
// ---------------------------------------------------------------------------
__device__ float g_energy[(size_t)BATCH * NDIM * NDIM];            // 134 MB
__device__ uint4 g_hhi[524288];   // h hi bf16
__device__ uint4 g_hlo[524288];   // h lo bf16
__device__ int   g_cnt[BATCH * NT];  // per (batch, tile-row) tiles done (goal 16)

// ---------------------------------------------------------------------------
// Kernel 0: split h -> hi/lo bf16; block 0 zeroes counters (every replay).
// ---------------------------------------------------------------------------
__global__ void __launch_bounds__(256)
convert_kernel(const float4* __restrict__ h4)
{
    if (blockIdx.x == 0 && threadIdx.x < BATCH * NT)
        g_cnt[threadIdx.x] = 0;

    const int base = blockIdx.x * 512 + threadIdx.x;
    #pragma unroll
    for (int i = 0; i < 2; ++i) {
        const int f = base + i * 256;
        const float4 v = h4[f];
        __nv_bfloat16 hx = __float2bfloat16_rn(v.x);
        __nv_bfloat16 hy = __float2bfloat16_rn(v.y);
        __nv_bfloat16 hz = __float2bfloat16_rn(v.z);
        __nv_bfloat16 hw = __float2bfloat16_rn(v.w);
        float lx = v.x - __bfloat162float(hx);
        float ly = v.y - __bfloat162float(hy);
        float lz = v.z - __bfloat162float(hz);
        float lw = v.w - __bfloat162float(hw);
        __nv_bfloat162 hi01 = __nv_bfloat162(hx, hy);
        __nv_bfloat162 hi23 = __nv_bfloat162(hz, hw);
        __nv_bfloat162 lo01 = __floats2bfloat162_rn(lx, ly);
        __nv_bfloat162 lo23 = __floats2bfloat162_rn(lz, lw);
        uint2 uh, ul;
        uh.x = *reinterpret_cast<uint32_t*>(&hi01);
        uh.y = *reinterpret_cast<uint32_t*>(&hi23);
        ul.x = *reinterpret_cast<uint32_t*>(&lo01);
        ul.y = *reinterpret_cast<uint32_t*>(&lo23);
        reinterpret_cast<uint2*>(g_hhi)[f] = uh;
        reinterpret_cast<uint2*>(g_hlo)[f] = ul;
    }
}

// ---------------------------------------------------------------------------
// mma.sync / ldmatrix / cp.async helpers (compute_100-safe)
// ---------------------------------------------------------------------------
__device__ __forceinline__ uint32_t smem_u32(const void* p) {
    uint32_t a;
    asm("{ .reg .u64 t; cvta.to.shared.u64 t, %1; cvt.u32.u64 %0, t; }"
        : "=r"(a) : "l"(p));
    return a;
}

__device__ __forceinline__ void ldsm_x4(uint32_t* r, uint32_t addr) {
    asm volatile("ldmatrix.sync.aligned.m8n8.x4.shared.b16 {%0,%1,%2,%3}, [%4];"
                 : "=r"(r[0]), "=r"(r[1]), "=r"(r[2]), "=r"(r[3]) : "r"(addr));
}

__device__ __forceinline__ void mma16816(float* d, const uint32_t* a,
                                         const uint32_t* b) {
    asm volatile("mma.sync.aligned.m16n8k16.row.col.f32.bf16.bf16.f32 "
                 "{%0,%1,%2,%3}, {%4,%5,%6,%7}, {%8,%9}, {%0,%1,%2,%3};"
                 : "+f"(d[0]), "+f"(d[1]), "+f"(d[2]), "+f"(d[3])
                 : "r"(a[0]), "r"(a[1]), "r"(a[2]), "r"(a[3]),
                   "r"(b[0]), "r"(b[1]));
}

__device__ __forceinline__ void cp_async16(uint32_t smem_dst, const void* gptr) {
    asm volatile("cp.async.cg.shared.global [%0], [%1], 16;\n"
                 :: "r"(smem_dst), "l"(__cvta_generic_to_global(gptr))
                 : "memory");
}
#define CP_COMMIT() asm volatile("cp.async.commit_group;\n" ::: "memory")
#define CP_WAIT(n)  asm volatile("cp.async.wait_group %0;\n" :: "n"(n) : "memory")

__device__ __forceinline__ uint32_t swz(int row, int kc) {
    return (uint32_t)(row * 64 + ((kc ^ ((row >> 1) & 3)) << 4));
}

// ---------------------------------------------------------------------------
// Kernel 1: SYRK energy[b] = h[b]*h[b]^T via split-bf16 3-MMA (mma.sync).
// R10 structure exactly (3-stage ring, 1 barrier/chunk, 2 CTAs/SM) plus:
//  - griddepcontrol.launch_dependents at entry (PDL handshake)
//  - fenced per-(batch,row-block) counter publish after stores
// ---------------------------------------------------------------------------
#define STAGE_BYTES 32768           // 4 arrays x 128 rows x 64B
#define ARR_BYTES   8192
#define SYRK_SMEM   (3 * STAGE_BYTES)   // 98304 >= epilogue 128*129*4=66048

__device__ __forceinline__ void load_stage(uint32_t sm_stage, int a_row0,
                                           int b_row0, int c, int tid,
                                           int batch4)
{
    #pragma unroll
    for (int i = 0; i < 8; ++i) {
        const int id  = tid + i * 256;      // 0..2047
        const int arr = id >> 9;            // 0=Ahi 1=Alo 2=Bhi 3=Blo
        const int cid = id & 511;
        const int row = cid >> 2;
        const int ch  = cid & 3;
        const uint32_t dst = sm_stage + arr * ARR_BYTES + swz(row, ch);
        const int grow = ((arr < 2) ? a_row0 : b_row0) + row;
        const uint4* src = ((arr & 1) ? g_hlo : g_hhi)
                           + batch4 + grow * 32 + c * 4 + ch;
        cp_async16(dst, src);
    }
}

__global__ void __launch_bounds__(256, 2)
syrk_mma_kernel()
{
    // PDL: signal that this block has launched; dependent (softmax) kernel
    // may begin launching once ALL syrk blocks have executed this.
    asm volatile("griddepcontrol.launch_dependents;" ::: "memory");

    extern __shared__ char smc[];
    const uint32_t smem_base = smem_u32(smc);
    const int tid  = threadIdx.x;
    const int wid  = tid >> 5;
    const int lane = tid & 31;
    const int b    = blockIdx.y;

    // decode (ti, tj), ti <= tj
    int p = blockIdx.x;
    int ti = 0;
    while (p >= (NT - ti)) { p -= (NT - ti); ++ti; }
    const int tj = ti + p;

    const int a_base = ti * TILE;
    const int b_base = tj * TILE;
    const int batch4 = b * 65536;           // uint4 offset of batch

    const int wm = (wid & 3) * 32;          // warp row origin in tile
    const int wn = (wid >> 2) * 64;         // warp col origin in tile

    float acc[2][8][4];
    #pragma unroll
    for (int mt = 0; mt < 2; ++mt)
        #pragma unroll
        for (int nt = 0; nt < 8; ++nt)
            #pragma unroll
            for (int q = 0; q < 4; ++q)
                acc[mt][nt][q] = 0.0f;

    // prime two stages (ring slots 0, 1)
    load_stage(smem_base,               a_base, b_base, 0, tid, batch4);
    CP_COMMIT();
    load_stage(smem_base + STAGE_BYTES, a_base, b_base, 1, tid, batch4);
    CP_COMMIT();

    // ldmatrix per-lane address components
    const int r8   = lane & 7;
    const int a_dr = (lane & 8);            // (grp&1)<<3
    const int a_dk = (lane >> 4);           // grp>>1
    const int b_dr = (lane & 16) >> 1;      // (grp>>1)<<3
    const int b_dk = (lane >> 3) & 1;      // grp&1

    #pragma unroll 1
    for (int c = 0; c < 8; ++c) {
        if (c < 7) { CP_WAIT(1); } else { CP_WAIT(0); }
        __syncthreads();            // the ONLY barrier per chunk

        const uint32_t sb  = smem_base + (uint32_t)(c % 3) * STAGE_BYTES;
        const uint32_t sAh = sb;
        const uint32_t sAl = sb + ARR_BYTES;
        const uint32_t sBh = sb + 2 * ARR_BYTES;
        const uint32_t sBl = sb + 3 * ARR_BYTES;

        // prefetch chunk c+2 into ring slot (c+2)%3 (disjoint, no WAR barrier)
        if (c + 2 < 8) {
            load_stage(smem_base + (uint32_t)((c + 2) % 3) * STAGE_BYTES,
                       a_base, b_base, c + 2, tid, batch4);
        }
        CP_COMMIT();

        #pragma unroll
        for (int ks = 0; ks < 2; ++ks) {
            uint32_t ahi[2][4], alo[2][4], bf[4][4];

            #pragma unroll
            for (int mt = 0; mt < 2; ++mt) {
                const int row = wm + mt * 16 + a_dr + r8;
                const int kc  = 2 * ks + a_dk;
                const uint32_t off = swz(row, kc);
                ldsm_x4(ahi[mt], sAh + off);
                ldsm_x4(alo[mt], sAl + off);
            }
            #pragma unroll
            for (int np = 0; np < 4; ++np) {
                const int row = wn + np * 16 + b_dr + r8;
                const int kc  = 2 * ks + b_dk;
                ldsm_x4(bf[np], sBh + swz(row, kc));
            }
            // hh + lh
            #pragma unroll
            for (int mt = 0; mt < 2; ++mt)
                #pragma unroll
                for (int np = 0; np < 4; ++np) {
                    mma16816(acc[mt][2 * np],     ahi[mt], &bf[np][0]);
                    mma16816(acc[mt][2 * np + 1], ahi[mt], &bf[np][2]);
                    mma16816(acc[mt][2 * np],     alo[mt], &bf[np][0]);
                    mma16816(acc[mt][2 * np + 1], alo[mt], &bf[np][2]);
                }
            // B lo over same regs
            #pragma unroll
            for (int np = 0; np < 4; ++np) {
                const int row = wn + np * 16 + b_dr + r8;
                const int kc  = 2 * ks + b_dk;
                ldsm_x4(bf[np], sBl + swz(row, kc));
            }
            // hl
            #pragma unroll
            for (int mt = 0; mt < 2; ++mt)
                #pragma unroll
                for (int np = 0; np < 4; ++np) {
                    mma16816(acc[mt][2 * np],     ahi[mt], &bf[np][0]);
                    mma16816(acc[mt][2 * np + 1], ahi[mt], &bf[np][2]);
                }
        }
    }

    // all warps must finish reading stages before sD overwrites them
    __syncthreads();

    // ---------------- epilogue: acc -> sD[128][129] -> gmem ----------------
    float* sD = reinterpret_cast<float*>(smc);
    {
        const int rq = lane >> 2;           // 0..7
        const int cq = (lane & 3) * 2;
        #pragma unroll
        for (int mt = 0; mt < 2; ++mt) {
            const int r0 = wm + mt * 16 + rq;
            #pragma unroll
            for (int nt = 0; nt < 8; ++nt) {
                const int cc = wn + nt * 8 + cq;
                sD[r0 * 129 + cc]           = acc[mt][nt][0];
                sD[r0 * 129 + cc + 1]       = acc[mt][nt][1];
                sD[(r0 + 8) * 129 + cc]     = acc[mt][nt][2];
                sD[(r0 + 8) * 129 + cc + 1] = acc[mt][nt][3];
            }
        }
    }
    __syncthreads();

    float* eb = g_energy + (size_t)b * NDIM * NDIM;

    // direct tile: fully coalesced float4 streaming stores
    #pragma unroll 4
    for (int i = 0; i < 16; ++i) {
        const int idx = tid + i * 256;
        const int r  = idx >> 5;
        const int c4 = (idx & 31) * 4;
        float4 v = make_float4(sD[r * 129 + c4 + 0], sD[r * 129 + c4 + 1],
                               sD[r * 129 + c4 + 2], sD[r * 129 + c4 + 3]);
        __stcs(reinterpret_cast<float4*>(
            &eb[(size_t)(a_base + r) * NDIM + b_base + c4]), v);
    }

    // mirror tile (transpose through smem), skip diagonal
    if (ti != tj) {
        #pragma unroll 4
        for (int i = 0; i < 16; ++i) {
            const int idx = tid + i * 256;
            const int r2 = idx >> 5;
            const int c4 = (idx & 31) * 4;
            float4 v = make_float4(sD[(c4 + 0) * 129 + r2], sD[(c4 + 1) * 129 + r2],
                                   sD[(c4 + 2) * 129 + r2], sD[(c4 + 3) * 129 + r2]);
            __stcs(reinterpret_cast<float4*>(
                &eb[(size_t)(b_base + r2) * NDIM + a_base + c4]), v);
        }
    }

    // publish: release (fence per thread, barrier, single-thread atomics)
    __threadfence();
    __syncthreads();
    if (tid == 0) {
        atomicAdd(&g_cnt[b * NT + ti], 1);
        if (ti != tj) atomicAdd(&g_cnt[b * NT + tj], 1);
    }
}

// ---------------------------------------------------------------------------
// Kernel 2: softmax (R10 2-row version) + entry gate on production counter.
// Launched with ProgrammaticStreamSerialization: may start while syrk's
// last wave still runs; the gate provides the data dependency.
// ---------------------------------------------------------------------------
__device__ __forceinline__ void red2_max(float mv[2], float* red,
                                         int wid, int lid)
{
    #pragma unroll
    for (int r = 0; r < 2; ++r)
        #pragma unroll
        for (int o = 16; o > 0; o >>= 1)
            mv[r] = fmaxf(mv[r], __shfl_xor_sync(0xFFFFFFFFu, mv[r], o));
    if (lid == 0) { red[wid * 2] = mv[0]; red[wid * 2 + 1] = mv[1]; }
    __syncthreads();
    #pragma unroll
    for (int r = 0; r < 2; ++r) {
        float v = red[r];
        #pragma unroll
        for (int w = 1; w < 8; ++w) v = fmaxf(v, red[w * 2 + r]);
        mv[r] = v;
    }
    __syncthreads();
}

__device__ __forceinline__ void red2_sum(float sv[2], float* red,
                                         int wid, int lid)
{
    #pragma unroll
    for (int r = 0; r < 2; ++r)
        #pragma unroll
        for (int o = 16; o > 0; o >>= 1)
            sv[r] += __shfl_xor_sync(0xFFFFFFFFu, sv[r], o);
    if (lid == 0) { red[wid * 2] = sv[0]; red[wid * 2 + 1] = sv[1]; }
    __syncthreads();
    #pragma unroll
    for (int r = 0; r < 2; ++r) {
        float v = red[r];
        #pragma unroll
        for (int w = 1; w < 8; ++w) v += red[w * 2 + r];
        sv[r] = v;
    }
    __syncthreads();
}

__global__ void __launch_bounds__(256)
softmax_kernel(const float* __restrict__ adj, float* __restrict__ out)
{
    const size_t row0 = (size_t)blockIdx.x * 2;
    __shared__ float red[16];
    __shared__ int ready;
    const int tid = threadIdx.x;
    const int wid = tid >> 5;
    const int lid = tid & 31;

    // gate: wait until all 16 tiles of this (batch,row-block) are published
    {
        const int b  = (int)(row0 >> 11);          // 2048 rows per batch
        const int rb = (int)((row0 & 2047) >> 7);  // 128-row block
        if (tid == 0) {
            volatile int* c = &g_cnt[b * NT + rb];
            while (*c < NT) __nanosleep(128);
            ready = 1;
        }
        __syncthreads();
        (void)ready;
        __threadfence();   // acquire: order energy reads after counter
    }

    float4 ev[2][2], av[2][2];
    #pragma unroll
    for (int r = 0; r < 2; ++r) {
        const float4* e4 = reinterpret_cast<const float4*>(
            g_energy + (row0 + r) * NDIM);
        const float4* a4 = reinterpret_cast<const float4*>(
            adj + (row0 + r) * NDIM);
        ev[r][0] = __ldcs(e4 + tid);
        ev[r][1] = __ldcs(e4 + tid + 256);
        av[r][0] = __ldcs(a4 + tid);
        av[r][1] = __ldcs(a4 + tid + 256);
    }

    float m1[2];
    #pragma unroll
    for (int r = 0; r < 2; ++r)
        m1[r] = fmaxf(fmaxf(fmaxf(ev[r][0].x, ev[r][0].y),
                            fmaxf(ev[r][0].z, ev[r][0].w)),
                      fmaxf(fmaxf(ev[r][1].x, ev[r][1].y),
                            fmaxf(ev[r][1].z, ev[r][1].w)));
    red2_max(m1, red, wid, lid);

    float t[2][8], m2[2];
    #pragma unroll
    for (int r = 0; r < 2; ++r) {
        t[r][0] = (m1[r] - ev[r][0].x) * av[r][0].x;
        t[r][1] = (m1[r] - ev[r][0].y) * av[r][0].y;
        t[r][2] = (m1[r] - ev[r][0].z) * av[r][0].z;
        t[r][3] = (m1[r] - ev[r][0].w) * av[r][0].w;
        t[r][4] = (m1[r] - ev[r][1].x) * av[r][1].x;
        t[r][5] = (m1[r] - ev[r][1].y) * av[r][1].y;
        t[r][6] = (m1[r] - ev[r][1].z) * av[r][1].z;
        t[r][7] = (m1[r] - ev[r][1].w) * av[r][1].w;
        float mm = t[r][0];
        #pragma unroll
        for (int i = 1; i < 8; ++i) mm = fmaxf(mm, t[r][i]);
        m2[r] = mm;
    }
    red2_max(m2, red, wid, lid);

    float sv[2];
    #pragma unroll
    for (int r = 0; r < 2; ++r) {
        float s = 0.0f;
        #pragma unroll
        for (int i = 0; i < 8; ++i) { t[r][i] = __expf(t[r][i] - m2[r]); s += t[r][i]; }
        sv[r] = s;
    }
    red2_sum(sv, red, wid, lid);

    #pragma unroll
    for (int r = 0; r < 2; ++r) {
        const float inv = 1.0f / sv[r];
        float4* o4 = reinterpret_cast<float4*>(out + (row0 + r) * NDIM);
        __stcs(o4 + tid, make_float4(t[r][0] * inv, t[r][1] * inv,
                                     t[r][2] * inv, t[r][3] * inv));
        __stcs(o4 + tid + 256, make_float4(t[r][4] * inv, t[r][5] * inv,
                                           t[r][6] * inv, t[r][7] * inv));
    }
}

// ---------------------------------------------------------------------------
extern "C" void kernel_launch(void* const* d_in, const int* in_sizes, int n_in,
                              void* d_out, int out_size)
{
    const float* h   = (const float*)d_in[0];   // [8, 2048, 256]
    const float* adj = (const float*)d_in[1];   // [8, 2048, 2048]
    float*       out = (float*)d_out;           // [8, 2048, 2048]
    (void)in_sizes; (void)n_in; (void)out_size;

    // Unconditional (no static guard). Host-side, idempotent, capture-safe.
    cudaFuncSetAttribute(syrk_mma_kernel,
                         cudaFuncAttributeMaxDynamicSharedMemorySize,
                         SYRK_SMEM);

    convert_kernel<<<2048, 256>>>(reinterpret_cast<const float4*>(h));

    dim3 g1(NPAIR, BATCH);
    syrk_mma_kernel<<<g1, 256, SYRK_SMEM>>>();

    // softmax with Programmatic Stream Serialization: allowed to launch while
    // syrk is still running (after all syrk blocks executed
    // griddepcontrol.launch_dependents); data dependency held by g_cnt gates.
    {
        cudaLaunchConfig_t cfg = {};
        cfg.gridDim  = dim3(BATCH * NDIM / 2);
        cfg.blockDim = dim3(256);
        cfg.dynamicSmemBytes = 0;
        cfg.stream = 0;
        cudaLaunchAttribute attrs[1];
        attrs[0].id = cudaLaunchAttributeProgrammaticStreamSerialization;
        attrs[0].val.programmaticStreamSerializationAllowed = 1;
        cfg.attrs = attrs;
        cfg.numAttrs = 1;
        cudaLaunchKernelEx(&cfg, softmax_kernel, adj, out);
    }
}

// round 13
// speedup vs baseline: 1.2165x; 1.0032x over previous
#include <cuda_runtime.h>
#include <cuda_bf16.h>
#include <cfloat>
#include <cstdint>

// Problem shape (fixed): B=8, N=2048, D=256
#define BATCH 8
#define NDIM  2048
#define DDIM  256

#define TILE 128
#define NT   (NDIM / TILE)               // 16
#define NPAIR ((NT * (NT + 1)) / 2)      // 136 upper-tri tile pairs

// ---------------------------------------------------------------------------
// Device scratch (allocation-free)
// ---------------------------------------------------------------------------
__device__ float g_energy[(size_t)BATCH * NDIM * NDIM];            // 134 MB
__device__ uint4 g_hhi[524288];   // h hi bf16
__device__ uint4 g_hlo[524288];   // h lo bf16
__device__ int   g_cnt[BATCH * NT];  // per (batch, tile-row) tiles done (goal 16)

// ---------------------------------------------------------------------------
// Kernel 0: split h -> hi/lo bf16; block 0 zeroes counters (every replay).
// Ends with PDL launch_dependents so syrk may begin launching.
// ---------------------------------------------------------------------------
__global__ void __launch_bounds__(256)
convert_kernel(const float4* __restrict__ h4)
{
    if (blockIdx.x == 0 && threadIdx.x < BATCH * NT)
        g_cnt[threadIdx.x] = 0;

    const int base = blockIdx.x * 512 + threadIdx.x;
    #pragma unroll
    for (int i = 0; i < 2; ++i) {
        const int f = base + i * 256;
        const float4 v = h4[f];
        __nv_bfloat16 hx = __float2bfloat16_rn(v.x);
        __nv_bfloat16 hy = __float2bfloat16_rn(v.y);
        __nv_bfloat16 hz = __float2bfloat16_rn(v.z);
        __nv_bfloat16 hw = __float2bfloat16_rn(v.w);
        float lx = v.x - __bfloat162float(hx);
        float ly = v.y - __bfloat162float(hy);
        float lz = v.z - __bfloat162float(hz);
        float lw = v.w - __bfloat162float(hw);
        __nv_bfloat162 hi01 = __nv_bfloat162(hx, hy);
        __nv_bfloat162 hi23 = __nv_bfloat162(hz, hw);
        __nv_bfloat162 lo01 = __floats2bfloat162_rn(lx, ly);
        __nv_bfloat162 lo23 = __floats2bfloat162_rn(lz, lw);
        uint2 uh, ul;
        uh.x = *reinterpret_cast<uint32_t*>(&hi01);
        uh.y = *reinterpret_cast<uint32_t*>(&hi23);
        ul.x = *reinterpret_cast<uint32_t*>(&lo01);
        ul.y = *reinterpret_cast<uint32_t*>(&lo23);
        reinterpret_cast<uint2*>(g_hhi)[f] = uh;
        reinterpret_cast<uint2*>(g_hlo)[f] = ul;
    }

    asm volatile("griddepcontrol.launch_dependents;" ::: "memory");
}

// ---------------------------------------------------------------------------
// mma.sync / ldmatrix / cp.async helpers (compute_100-safe)
// ---------------------------------------------------------------------------
__device__ __forceinline__ uint32_t smem_u32(const void* p) {
    uint32_t a;
    asm("{ .reg .u64 t; cvta.to.shared.u64 t, %1; cvt.u32.u64 %0, t; }"
        : "=r"(a) : "l"(p));
    return a;
}

__device__ __forceinline__ void ldsm_x4(uint32_t* r, uint32_t addr) {
    asm volatile("ldmatrix.sync.aligned.m8n8.x4.shared.b16 {%0,%1,%2,%3}, [%4];"
                 : "=r"(r[0]), "=r"(r[1]), "=r"(r[2]), "=r"(r[3]) : "r"(addr));
}

__device__ __forceinline__ void mma16816(float* d, const uint32_t* a,
                                         const uint32_t* b) {
    asm volatile("mma.sync.aligned.m16n8k16.row.col.f32.bf16.bf16.f32 "
                 "{%0,%1,%2,%3}, {%4,%5,%6,%7}, {%8,%9}, {%0,%1,%2,%3};"
                 : "+f"(d[0]), "+f"(d[1]), "+f"(d[2]), "+f"(d[3])
                 : "r"(a[0]), "r"(a[1]), "r"(a[2]), "r"(a[3]),
                   "r"(b[0]), "r"(b[1]));
}

__device__ __forceinline__ void cp_async16(uint32_t smem_dst, const void* gptr) {
    asm volatile("cp.async.cg.shared.global [%0], [%1], 16;\n"
                 :: "r"(smem_dst), "l"(__cvta_generic_to_global(gptr))
                 : "memory");
}
#define CP_COMMIT() asm volatile("cp.async.commit_group;\n" ::: "memory")
#define CP_WAIT(n)  asm volatile("cp.async.wait_group %0;\n" :: "n"(n) : "memory")

__device__ __forceinline__ uint32_t swz(int row, int kc) {
    return (uint32_t)(row * 64 + ((kc ^ ((row >> 1) & 3)) << 4));
}

// ---------------------------------------------------------------------------
// Kernel 1: SYRK energy[b] = h[b]*h[b]^T via split-bf16 3-MMA (mma.sync).
// R10 mainloop (3-stage ring, 1 barrier/chunk, 2 CTAs/SM).
// PDL: waits on convert, then releases softmax launch.
// ---------------------------------------------------------------------------
#define STAGE_BYTES 32768           // 4 arrays x 128 rows x 64B
#define ARR_BYTES   8192
#define SYRK_SMEM   (3 * STAGE_BYTES)   // 98304 >= epilogue 128*129*4=66048

__device__ __forceinline__ void load_stage(uint32_t sm_stage, int a_row0,
                                           int b_row0, int c, int tid,
                                           int batch4)
{
    #pragma unroll
    for (int i = 0; i < 8; ++i) {
        const int id  = tid + i * 256;      // 0..2047
        const int arr = id >> 9;            // 0=Ahi 1=Alo 2=Bhi 3=Blo
        const int cid = id & 511;
        const int row = cid >> 2;
        const int ch  = cid & 3;
        const uint32_t dst = sm_stage + arr * ARR_BYTES + swz(row, ch);
        const int grow = ((arr < 2) ? a_row0 : b_row0) + row;
        const uint4* src = ((arr & 1) ? g_hlo : g_hhi)
                           + batch4 + grow * 32 + c * 4 + ch;
        cp_async16(dst, src);
    }
}

__global__ void __launch_bounds__(256, 2)
syrk_mma_kernel()
{
    // PDL: wait for convert's data (and its counter zeroing) to be visible,
    // THEN allow softmax to start launching. Order is load-bearing: softmax
    // must not launch before the counters are zeroed.
    asm volatile("griddepcontrol.wait;" ::: "memory");
    asm volatile("griddepcontrol.launch_dependents;" ::: "memory");

    extern __shared__ char smc[];
    const uint32_t smem_base = smem_u32(smc);
    const int tid  = threadIdx.x;
    const int wid  = tid >> 5;
    const int lane = tid & 31;
    const int b    = blockIdx.y;

    // decode (ti, tj), ti <= tj
    int p = blockIdx.x;
    int ti = 0;
    while (p >= (NT - ti)) { p -= (NT - ti); ++ti; }
    const int tj = ti + p;

    const int a_base = ti * TILE;
    const int b_base = tj * TILE;
    const int batch4 = b * 65536;           // uint4 offset of batch

    const int wm = (wid & 3) * 32;          // warp row origin in tile
    const int wn = (wid >> 2) * 64;         // warp col origin in tile

    float acc[2][8][4];
    #pragma unroll
    for (int mt = 0; mt < 2; ++mt)
        #pragma unroll
        for (int nt = 0; nt < 8; ++nt)
            #pragma unroll
            for (int q = 0; q < 4; ++q)
                acc[mt][nt][q] = 0.0f;

    // prime two stages (ring slots 0, 1)
    load_stage(smem_base,               a_base, b_base, 0, tid, batch4);
    CP_COMMIT();
    load_stage(smem_base + STAGE_BYTES, a_base, b_base, 1, tid, batch4);
    CP_COMMIT();

    // ldmatrix per-lane address components
    const int r8   = lane & 7;
    const int a_dr = (lane & 8);            // (grp&1)<<3
    const int a_dk = (lane >> 4);           // grp>>1
    const int b_dr = (lane & 16) >> 1;      // (grp>>1)<<3
    const int b_dk = (lane >> 3) & 1;       // grp&1

    #pragma unroll 1
    for (int c = 0; c < 8; ++c) {
        if (c < 7) { CP_WAIT(1); } else { CP_WAIT(0); }
        __syncthreads();            // the ONLY barrier per chunk

        const uint32_t sb  = smem_base + (uint32_t)(c % 3) * STAGE_BYTES;
        const uint32_t sAh = sb;
        const uint32_t sAl = sb + ARR_BYTES;
        const uint32_t sBh = sb + 2 * ARR_BYTES;
        const uint32_t sBl = sb + 3 * ARR_BYTES;

        // prefetch chunk c+2 into ring slot (c+2)%3 (disjoint, no WAR barrier)
        if (c + 2 < 8) {
            load_stage(smem_base + (uint32_t)((c + 2) % 3) * STAGE_BYTES,
                       a_base, b_base, c + 2, tid, batch4);
        }
        CP_COMMIT();

        #pragma unroll
        for (int ks = 0; ks < 2; ++ks) {
            uint32_t ahi[2][4], alo[2][4], bf[4][4];

            #pragma unroll
            for (int mt = 0; mt < 2; ++mt) {
                const int row = wm + mt * 16 + a_dr + r8;
                const int kc  = 2 * ks + a_dk;
                const uint32_t off = swz(row, kc);
                ldsm_x4(ahi[mt], sAh + off);
                ldsm_x4(alo[mt], sAl + off);
            }
            #pragma unroll
            for (int np = 0; np < 4; ++np) {
                const int row = wn + np * 16 + b_dr + r8;
                const int kc  = 2 * ks + b_dk;
                ldsm_x4(bf[np], sBh + swz(row, kc));
            }
            // hh + lh
            #pragma unroll
            for (int mt = 0; mt < 2; ++mt)
                #pragma unroll
                for (int np = 0; np < 4; ++np) {
                    mma16816(acc[mt][2 * np],     ahi[mt], &bf[np][0]);
                    mma16816(acc[mt][2 * np + 1], ahi[mt], &bf[np][2]);
                    mma16816(acc[mt][2 * np],     alo[mt], &bf[np][0]);
                    mma16816(acc[mt][2 * np + 1], alo[mt], &bf[np][2]);
                }
            // B lo over same regs
            #pragma unroll
            for (int np = 0; np < 4; ++np) {
                const int row = wn + np * 16 + b_dr + r8;
                const int kc  = 2 * ks + b_dk;
                ldsm_x4(bf[np], sBl + swz(row, kc));
            }
            // hl
            #pragma unroll
            for (int mt = 0; mt < 2; ++mt)
                #pragma unroll
                for (int np = 0; np < 4; ++np) {
                    mma16816(acc[mt][2 * np],     ahi[mt], &bf[np][0]);
                    mma16816(acc[mt][2 * np + 1], ahi[mt], &bf[np][2]);
                }
        }
    }

    // all warps must finish reading stages before sD overwrites them
    __syncthreads();

    // ---------------- epilogue: acc -> sD[128][129] -> gmem ----------------
    float* sD = reinterpret_cast<float*>(smc);
    {
        const int rq = lane >> 2;           // 0..7
        const int cq = (lane & 3) * 2;
        #pragma unroll
        for (int mt = 0; mt < 2; ++mt) {
            const int r0 = wm + mt * 16 + rq;
            #pragma unroll
            for (int nt = 0; nt < 8; ++nt) {
                const int cc = wn + nt * 8 + cq;
                sD[r0 * 129 + cc]           = acc[mt][nt][0];
                sD[r0 * 129 + cc + 1]       = acc[mt][nt][1];
                sD[(r0 + 8) * 129 + cc]     = acc[mt][nt][2];
                sD[(r0 + 8) * 129 + cc + 1] = acc[mt][nt][3];
            }
        }
    }
    __syncthreads();

    float* eb = g_energy + (size_t)b * NDIM * NDIM;

    // direct tile: fully coalesced float4 streaming stores
    #pragma unroll 4
    for (int i = 0; i < 16; ++i) {
        const int idx = tid + i * 256;
        const int r  = idx >> 5;
        const int c4 = (idx & 31) * 4;
        float4 v = make_float4(sD[r * 129 + c4 + 0], sD[r * 129 + c4 + 1],
                               sD[r * 129 + c4 + 2], sD[r * 129 + c4 + 3]);
        __stcs(reinterpret_cast<float4*>(
            &eb[(size_t)(a_base + r) * NDIM + b_base + c4]), v);
    }

    // mirror tile (transpose through smem), skip diagonal
    if (ti != tj) {
        #pragma unroll 4
        for (int i = 0; i < 16; ++i) {
            const int idx = tid + i * 256;
            const int r2 = idx >> 5;
            const int c4 = (idx & 31) * 4;
            float4 v = make_float4(sD[(c4 + 0) * 129 + r2], sD[(c4 + 1) * 129 + r2],
                                   sD[(c4 + 2) * 129 + r2], sD[(c4 + 3) * 129 + r2]);
            __stcs(reinterpret_cast<float4*>(
                &eb[(size_t)(b_base + r2) * NDIM + a_base + c4]), v);
        }
    }

    // publish: release (fence per thread, barrier, single-thread atomics)
    __threadfence();
    __syncthreads();
    if (tid == 0) {
        atomicAdd(&g_cnt[b * NT + ti], 1);
        if (ti != tj) atomicAdd(&g_cnt[b * NT + tj], 1);
    }
}

// ---------------------------------------------------------------------------
// Kernel 2: softmax, counter-gated, PDL-early-launched.
//  - adj loads issued BEFORE the gate (independent of syrk)
//  - consumption order: first 2048 blocks take oldest rows forward (overlap
//    syrk tail); remaining blocks take rows newest-first (harvest L2).
// ---------------------------------------------------------------------------
__device__ __forceinline__ void red2_max(float mv[2], float* red,
                                         int wid, int lid)
{
    #pragma unroll
    for (int r = 0; r < 2; ++r)
        #pragma unroll
        for (int o = 16; o > 0; o >>= 1)
            mv[r] = fmaxf(mv[r], __shfl_xor_sync(0xFFFFFFFFu, mv[r], o));
    if (lid == 0) { red[wid * 2] = mv[0]; red[wid * 2 + 1] = mv[1]; }
    __syncthreads();
    #pragma unroll
    for (int r = 0; r < 2; ++r) {
        float v = red[r];
        #pragma unroll
        for (int w = 1; w < 8; ++w) v = fmaxf(v, red[w * 2 + r]);
        mv[r] = v;
    }
    __syncthreads();
}

__device__ __forceinline__ void red2_sum(float sv[2], float* red,
                                         int wid, int lid)
{
    #pragma unroll
    for (int r = 0; r < 2; ++r)
        #pragma unroll
        for (int o = 16; o > 0; o >>= 1)
            sv[r] += __shfl_xor_sync(0xFFFFFFFFu, sv[r], o);
    if (lid == 0) { red[wid * 2] = sv[0]; red[wid * 2 + 1] = sv[1]; }
    __syncthreads();
    #pragma unroll
    for (int r = 0; r < 2; ++r) {
        float v = red[r];
        #pragma unroll
        for (int w = 1; w < 8; ++w) v += red[w * 2 + r];
        sv[r] = v;
    }
    __syncthreads();
}

__global__ void __launch_bounds__(256)
softmax_kernel(const float* __restrict__ adj, float* __restrict__ out)
{
    // chunk remap: forward prefix for tail overlap, reversed bulk for L2 reuse
    const int cid = blockIdx.x;                       // 0..8191
    const int chunk = (cid < 2048) ? cid : (10239 - cid);
    const size_t row0 = (size_t)chunk * 2;

    __shared__ float red[16];
    __shared__ int ready;
    const int tid = threadIdx.x;
    const int wid = tid >> 5;
    const int lid = tid & 31;

    // adj prefetch (independent of syrk) — in flight during the gate spin
    float4 av[2][2];
    #pragma unroll
    for (int r = 0; r < 2; ++r) {
        const float4* a4 = reinterpret_cast<const float4*>(
            adj + (row0 + r) * NDIM);
        av[r][0] = __ldcs(a4 + tid);
        av[r][1] = __ldcs(a4 + tid + 256);
    }

    // gate: wait until all 16 tiles of this (batch,row-block) are published
    {
        const int b  = (int)(row0 >> 11);          // 2048 rows per batch
        const int rb = (int)((row0 & 2047) >> 7);  // 128-row block
        if (tid == 0) {
            volatile int* c = &g_cnt[b * NT + rb];
            while (*c < NT) __nanosleep(128);
            ready = 1;
        }
        __syncthreads();
        (void)ready;
        __threadfence();   // acquire: order energy reads after counter
    }

    float4 ev[2][2];
    #pragma unroll
    for (int r = 0; r < 2; ++r) {
        const float4* e4 = reinterpret_cast<const float4*>(
            g_energy + (row0 + r) * NDIM);
        ev[r][0] = __ldcs(e4 + tid);
        ev[r][1] = __ldcs(e4 + tid + 256);
    }

    float m1[2];
    #pragma unroll
    for (int r = 0; r < 2; ++r)
        m1[r] = fmaxf(fmaxf(fmaxf(ev[r][0].x, ev[r][0].y),
                            fmaxf(ev[r][0].z, ev[r][0].w)),
                      fmaxf(fmaxf(ev[r][1].x, ev[r][1].y),
                            fmaxf(ev[r][1].z, ev[r][1].w)));
    red2_max(m1, red, wid, lid);

    float t[2][8], m2[2];
    #pragma unroll
    for (int r = 0; r < 2; ++r) {
        t[r][0] = (m1[r] - ev[r][0].x) * av[r][0].x;
        t[r][1] = (m1[r] - ev[r][0].y) * av[r][0].y;
        t[r][2] = (m1[r] - ev[r][0].z) * av[r][0].z;
        t[r][3] = (m1[r] - ev[r][0].w) * av[r][0].w;
        t[r][4] = (m1[r] - ev[r][1].x) * av[r][1].x;
        t[r][5] = (m1[r] - ev[r][1].y) * av[r][1].y;
        t[r][6] = (m1[r] - ev[r][1].z) * av[r][1].z;
        t[r][7] = (m1[r] - ev[r][1].w) * av[r][1].w;
        float mm = t[r][0];
        #pragma unroll
        for (int i = 1; i < 8; ++i) mm = fmaxf(mm, t[r][i]);
        m2[r] = mm;
    }
    red2_max(m2, red, wid, lid);

    float sv[2];
    #pragma unroll
    for (int r = 0; r < 2; ++r) {
        float s = 0.0f;
        #pragma unroll
        for (int i = 0; i < 8; ++i) { t[r][i] = __expf(t[r][i] - m2[r]); s += t[r][i]; }
        sv[r] = s;
    }
    red2_sum(sv, red, wid, lid);

    #pragma unroll
    for (int r = 0; r < 2; ++r) {
        const float inv = 1.0f / sv[r];
        float4* o4 = reinterpret_cast<float4*>(out + (row0 + r) * NDIM);
        __stcs(o4 + tid, make_float4(t[r][0] * inv, t[r][1] * inv,
                                     t[r][2] * inv, t[r][3] * inv));
        __stcs(o4 + tid + 256, make_float4(t[r][4] * inv, t[r][5] * inv,
                                           t[r][6] * inv, t[r][7] * inv));
    }
}

// ---------------------------------------------------------------------------
extern "C" void kernel_launch(void* const* d_in, const int* in_sizes, int n_in,
                              void* d_out, int out_size)
{
    const float* h   = (const float*)d_in[0];   // [8, 2048, 256]
    const float* adj = (const float*)d_in[1];   // [8, 2048, 2048]
    float*       out = (float*)d_out;           // [8, 2048, 2048]
    (void)in_sizes; (void)n_in; (void)out_size;

    // Unconditional (no static guard). Host-side, idempotent, capture-safe.
    cudaFuncSetAttribute(syrk_mma_kernel,
                         cudaFuncAttributeMaxDynamicSharedMemorySize,
                         SYRK_SMEM);

    convert_kernel<<<2048, 256>>>(reinterpret_cast<const float4*>(h));

    // syrk with PSS: launches while convert finishes; griddepcontrol.wait
    // inside syrk provides the data dependency on convert.
    {
        cudaLaunchConfig_t cfg = {};
        cfg.gridDim  = dim3(NPAIR, BATCH);
        cfg.blockDim = dim3(256);
        cfg.dynamicSmemBytes = SYRK_SMEM;
        cfg.stream = 0;
        cudaLaunchAttribute attrs[1];
        attrs[0].id = cudaLaunchAttributeProgrammaticStreamSerialization;
        attrs[0].val.programmaticStreamSerializationAllowed = 1;
        cfg.attrs = attrs;
        cfg.numAttrs = 1;
        cudaLaunchKernelEx(&cfg, syrk_mma_kernel);
    }

    // softmax with PSS: launches during syrk's last wave; per-row-block
    // counter gates provide the data dependency.
    {
        cudaLaunchConfig_t cfg = {};
        cfg.gridDim  = dim3(BATCH * NDIM / 2);
        cfg.blockDim = dim3(256);
        cfg.dynamicSmemBytes = 0;
        cfg.stream = 0;
        cudaLaunchAttribute attrs[1];
        attrs[0].id = cudaLaunchAttributeProgrammaticStreamSerialization;
        attrs[0].val.programmaticStreamSerializationAllowed = 1;
        cfg.attrs = attrs;
        cfg.numAttrs = 1;
        cudaLaunchKernelEx(&cfg, softmax_kernel, adj, out);
    }
}

// round 14
// speedup vs baseline: 1.2170x; 1.0004x over previous
#include <cuda_runtime.h>
#include <cuda_bf16.h>
#include <cfloat>
#include <cstdint>

// Problem shape (fixed): B=8, N=2048, D=256
#define BATCH 8
#define NDIM  2048
#define DDIM  256

#define TILE 128
#define NT   (NDIM / TILE)               // 16
#define NPAIR ((NT * (NT + 1)) / 2)      // 136 upper-tri tile pairs

// ---------------------------------------------------------------------------
// Device scratch (allocation-free)
// ---------------------------------------------------------------------------
__device__ float g_energy[(size_t)BATCH * NDIM * NDIM];            // 134 MB
__device__ uint4 g_hhi[524288];   // h hi bf16
__device__ uint4 g_hlo[524288];   // h lo bf16
__device__ int   g_cnt[BATCH * NT];  // per (batch, tile-row) tiles done (goal 16)

// ---------------------------------------------------------------------------
// Kernel 0: split h -> hi/lo bf16; block 0 zeroes counters (every replay).
// Ends with PDL launch_dependents so syrk may begin launching.
// ---------------------------------------------------------------------------
__global__ void __launch_bounds__(256)
convert_kernel(const float4* __restrict__ h4)
{
    if (blockIdx.x == 0 && threadIdx.x < BATCH * NT)
        g_cnt[threadIdx.x] = 0;

    const int base = blockIdx.x * 512 + threadIdx.x;
    #pragma unroll
    for (int i = 0; i < 2; ++i) {
        const int f = base + i * 256;
        const float4 v = h4[f];
        __nv_bfloat16 hx = __float2bfloat16_rn(v.x);
        __nv_bfloat16 hy = __float2bfloat16_rn(v.y);
        __nv_bfloat16 hz = __float2bfloat16_rn(v.z);
        __nv_bfloat16 hw = __float2bfloat16_rn(v.w);
        float lx = v.x - __bfloat162float(hx);
        float ly = v.y - __bfloat162float(hy);
        float lz = v.z - __bfloat162float(hz);
        float lw = v.w - __bfloat162float(hw);
        __nv_bfloat162 hi01 = __nv_bfloat162(hx, hy);
        __nv_bfloat162 hi23 = __nv_bfloat162(hz, hw);
        __nv_bfloat162 lo01 = __floats2bfloat162_rn(lx, ly);
        __nv_bfloat162 lo23 = __floats2bfloat162_rn(lz, lw);
        uint2 uh, ul;
        uh.x = *reinterpret_cast<uint32_t*>(&hi01);
        uh.y = *reinterpret_cast<uint32_t*>(&hi23);
        ul.x = *reinterpret_cast<uint32_t*>(&lo01);
        ul.y = *reinterpret_cast<uint32_t*>(&lo23);
        reinterpret_cast<uint2*>(g_hhi)[f] = uh;
        reinterpret_cast<uint2*>(g_hlo)[f] = ul;
    }

    asm volatile("griddepcontrol.launch_dependents;" ::: "memory");
}

// ---------------------------------------------------------------------------
// mma.sync / ldmatrix / cp.async helpers (compute_100-safe)
// ---------------------------------------------------------------------------
__device__ __forceinline__ uint32_t smem_u32(const void* p) {
    uint32_t a;
    asm("{ .reg .u64 t; cvta.to.shared.u64 t, %1; cvt.u32.u64 %0, t; }"
        : "=r"(a) : "l"(p));
    return a;
}

__device__ __forceinline__ void ldsm_x4(uint32_t* r, uint32_t addr) {
    asm volatile("ldmatrix.sync.aligned.m8n8.x4.shared.b16 {%0,%1,%2,%3}, [%4];"
                 : "=r"(r[0]), "=r"(r[1]), "=r"(r[2]), "=r"(r[3]) : "r"(addr));
}

__device__ __forceinline__ void mma16816(float* d, const uint32_t* a,
                                         const uint32_t* b) {
    asm volatile("mma.sync.aligned.m16n8k16.row.col.f32.bf16.bf16.f32 "
                 "{%0,%1,%2,%3}, {%4,%5,%6,%7}, {%8,%9}, {%0,%1,%2,%3};"
                 : "+f"(d[0]), "+f"(d[1]), "+f"(d[2]), "+f"(d[3])
                 : "r"(a[0]), "r"(a[1]), "r"(a[2]), "r"(a[3]),
                   "r"(b[0]), "r"(b[1]));
}

__device__ __forceinline__ void cp_async16(uint32_t smem_dst, const void* gptr) {
    asm volatile("cp.async.cg.shared.global [%0], [%1], 16;\n"
                 :: "r"(smem_dst), "l"(__cvta_generic_to_global(gptr))
                 : "memory");
}
#define CP_COMMIT() asm volatile("cp.async.commit_group;\n" ::: "memory")
#define CP_WAIT(n)  asm volatile("cp.async.wait_group %0;\n" :: "n"(n) : "memory")

__device__ __forceinline__ uint32_t swz(int row, int kc) {
    return (uint32_t)(row * 64 + ((kc ^ ((row >> 1) & 3)) << 4));
}

// ---------------------------------------------------------------------------
// Kernel 1: SYRK energy[b] = h[b]*h[b]^T via split-bf16 3-MMA (mma.sync).
// R13 structure; ks body reordered into three 16-MMA passes so each
// accumulator is revisited at distance 16 (RAW latency hidden), not 2.
// ---------------------------------------------------------------------------
#define STAGE_BYTES 32768           // 4 arrays x 128 rows x 64B
#define ARR_BYTES   8192
#define SYRK_SMEM   (3 * STAGE_BYTES)   // 98304 >= epilogue 128*129*4=66048

__device__ __forceinline__ void load_stage(uint32_t sm_stage, int a_row0,
                                           int b_row0, int c, int tid,
                                           int batch4)
{
    #pragma unroll
    for (int i = 0; i < 8; ++i) {
        const int id  = tid + i * 256;      // 0..2047
        const int arr = id >> 9;            // 0=Ahi 1=Alo 2=Bhi 3=Blo
        const int cid = id & 511;
        const int row = cid >> 2;
        const int ch  = cid & 3;
        const uint32_t dst = sm_stage + arr * ARR_BYTES + swz(row, ch);
        const int grow = ((arr < 2) ? a_row0 : b_row0) + row;
        const uint4* src = ((arr & 1) ? g_hlo : g_hhi)
                           + batch4 + grow * 32 + c * 4 + ch;
        cp_async16(dst, src);
    }
}

__global__ void __launch_bounds__(256, 2)
syrk_mma_kernel()
{
    // PDL: wait for convert's data (and counter zeroing), then release the
    // softmax launch. Order is load-bearing.
    asm volatile("griddepcontrol.wait;" ::: "memory");
    asm volatile("griddepcontrol.launch_dependents;" ::: "memory");

    extern __shared__ char smc[];
    const uint32_t smem_base = smem_u32(smc);
    const int tid  = threadIdx.x;
    const int wid  = tid >> 5;
    const int lane = tid & 31;
    const int b    = blockIdx.y;

    // decode (ti, tj), ti <= tj
    int p = blockIdx.x;
    int ti = 0;
    while (p >= (NT - ti)) { p -= (NT - ti); ++ti; }
    const int tj = ti + p;

    const int a_base = ti * TILE;
    const int b_base = tj * TILE;
    const int batch4 = b * 65536;           // uint4 offset of batch

    const int wm = (wid & 3) * 32;          // warp row origin in tile
    const int wn = (wid >> 2) * 64;         // warp col origin in tile

    float acc[2][8][4];
    #pragma unroll
    for (int mt = 0; mt < 2; ++mt)
        #pragma unroll
        for (int nt = 0; nt < 8; ++nt)
            #pragma unroll
            for (int q = 0; q < 4; ++q)
                acc[mt][nt][q] = 0.0f;

    // prime two stages (ring slots 0, 1)
    load_stage(smem_base,               a_base, b_base, 0, tid, batch4);
    CP_COMMIT();
    load_stage(smem_base + STAGE_BYTES, a_base, b_base, 1, tid, batch4);
    CP_COMMIT();

    // ldmatrix per-lane address components
    const int r8   = lane & 7;
    const int a_dr = (lane & 8);            // (grp&1)<<3
    const int a_dk = (lane >> 4);           // grp>>1
    const int b_dr = (lane & 16) >> 1;      // (grp>>1)<<3
    const int b_dk = (lane >> 3) & 1;       // grp&1

    #pragma unroll 1
    for (int c = 0; c < 8; ++c) {
        if (c < 7) { CP_WAIT(1); } else { CP_WAIT(0); }
        __syncthreads();            // the ONLY barrier per chunk

        const uint32_t sb  = smem_base + (uint32_t)(c % 3) * STAGE_BYTES;
        const uint32_t sAh = sb;
        const uint32_t sAl = sb + ARR_BYTES;
        const uint32_t sBh = sb + 2 * ARR_BYTES;
        const uint32_t sBl = sb + 3 * ARR_BYTES;

        // prefetch chunk c+2 into ring slot (c+2)%3 (disjoint, no WAR barrier)
        if (c + 2 < 8) {
            load_stage(smem_base + (uint32_t)((c + 2) % 3) * STAGE_BYTES,
                       a_base, b_base, c + 2, tid, batch4);
        }
        CP_COMMIT();

        #pragma unroll
        for (int ks = 0; ks < 2; ++ks) {
            uint32_t ahi[2][4], alo[2][4], bf[4][4];

            #pragma unroll
            for (int mt = 0; mt < 2; ++mt) {
                const int row = wm + mt * 16 + a_dr + r8;
                const int kc  = 2 * ks + a_dk;
                const uint32_t off = swz(row, kc);
                ldsm_x4(ahi[mt], sAh + off);
                ldsm_x4(alo[mt], sAl + off);
            }
            #pragma unroll
            for (int np = 0; np < 4; ++np) {
                const int row = wn + np * 16 + b_dr + r8;
                const int kc  = 2 * ks + b_dk;
                ldsm_x4(bf[np], sBh + swz(row, kc));
            }
            // PASS 1: hh — 16 MMAs, 16 distinct accumulators
            #pragma unroll
            for (int mt = 0; mt < 2; ++mt)
                #pragma unroll
                for (int np = 0; np < 4; ++np) {
                    mma16816(acc[mt][2 * np],     ahi[mt], &bf[np][0]);
                    mma16816(acc[mt][2 * np + 1], ahi[mt], &bf[np][2]);
                }
            // PASS 2: lh — same 16 accumulators revisited at distance 16
            #pragma unroll
            for (int mt = 0; mt < 2; ++mt)
                #pragma unroll
                for (int np = 0; np < 4; ++np) {
                    mma16816(acc[mt][2 * np],     alo[mt], &bf[np][0]);
                    mma16816(acc[mt][2 * np + 1], alo[mt], &bf[np][2]);
                }
            // reload B-lo over the same registers
            #pragma unroll
            for (int np = 0; np < 4; ++np) {
                const int row = wn + np * 16 + b_dr + r8;
                const int kc  = 2 * ks + b_dk;
                ldsm_x4(bf[np], sBl + swz(row, kc));
            }
            // PASS 3: hl — distance 16 again
            #pragma unroll
            for (int mt = 0; mt < 2; ++mt)
                #pragma unroll
                for (int np = 0; np < 4; ++np) {
                    mma16816(acc[mt][2 * np],     ahi[mt], &bf[np][0]);
                    mma16816(acc[mt][2 * np + 1], ahi[mt], &bf[np][2]);
                }
        }
    }

    // all warps must finish reading stages before sD overwrites them
    __syncthreads();

    // ---------------- epilogue: acc -> sD[128][129] -> gmem ----------------
    float* sD = reinterpret_cast<float*>(smc);
    {
        const int rq = lane >> 2;           // 0..7
        const int cq = (lane & 3) * 2;
        #pragma unroll
        for (int mt = 0; mt < 2; ++mt) {
            const int r0 = wm + mt * 16 + rq;
            #pragma unroll
            for (int nt = 0; nt < 8; ++nt) {
                const int cc = wn + nt * 8 + cq;
                sD[r0 * 129 + cc]           = acc[mt][nt][0];
                sD[r0 * 129 + cc + 1]       = acc[mt][nt][1];
                sD[(r0 + 8) * 129 + cc]     = acc[mt][nt][2];
                sD[(r0 + 8) * 129 + cc + 1] = acc[mt][nt][3];
            }
        }
    }
    __syncthreads();

    float* eb = g_energy + (size_t)b * NDIM * NDIM;

    // direct tile: fully coalesced float4 streaming stores
    #pragma unroll 4
    for (int i = 0; i < 16; ++i) {
        const int idx = tid + i * 256;
        const int r  = idx >> 5;
        const int c4 = (idx & 31) * 4;
        float4 v = make_float4(sD[r * 129 + c4 + 0], sD[r * 129 + c4 + 1],
                               sD[r * 129 + c4 + 2], sD[r * 129 + c4 + 3]);
        __stcs(reinterpret_cast<float4*>(
            &eb[(size_t)(a_base + r) * NDIM + b_base + c4]), v);
    }

    // mirror tile (transpose through smem), skip diagonal
    if (ti != tj) {
        #pragma unroll 4
        for (int i = 0; i < 16; ++i) {
            const int idx = tid + i * 256;
            const int r2 = idx >> 5;
            const int c4 = (idx & 31) * 4;
            float4 v = make_float4(sD[(c4 + 0) * 129 + r2], sD[(c4 + 1) * 129 + r2],
                                   sD[(c4 + 2) * 129 + r2], sD[(c4 + 3) * 129 + r2]);
            __stcs(reinterpret_cast<float4*>(
                &eb[(size_t)(b_base + r2) * NDIM + a_base + c4]), v);
        }
    }

    // publish: release (fence per thread, barrier, single-thread atomics)
    __threadfence();
    __syncthreads();
    if (tid == 0) {
        atomicAdd(&g_cnt[b * NT + ti], 1);
        if (ti != tj) atomicAdd(&g_cnt[b * NT + tj], 1);
    }
}

// ---------------------------------------------------------------------------
// Kernel 2: softmax, counter-gated, PDL-early-launched (R13 version).
// ---------------------------------------------------------------------------
__device__ __forceinline__ void red2_max(float mv[2], float* red,
                                         int wid, int lid)
{
    #pragma unroll
    for (int r = 0; r < 2; ++r)
        #pragma unroll
        for (int o = 16; o > 0; o >>= 1)
            mv[r] = fmaxf(mv[r], __shfl_xor_sync(0xFFFFFFFFu, mv[r], o));
    if (lid == 0) { red[wid * 2] = mv[0]; red[wid * 2 + 1] = mv[1]; }
    __syncthreads();
    #pragma unroll
    for (int r = 0; r < 2; ++r) {
        float v = red[r];
        #pragma unroll
        for (int w = 1; w < 8; ++w) v = fmaxf(v, red[w * 2 + r]);
        mv[r] = v;
    }
    __syncthreads();
}

__device__ __forceinline__ void red2_sum(float sv[2], float* red,
                                         int wid, int lid)
{
    #pragma unroll
    for (int r = 0; r < 2; ++r)
        #pragma unroll
        for (int o = 16; o > 0; o >>= 1)
            sv[r] += __shfl_xor_sync(0xFFFFFFFFu, sv[r], o);
    if (lid == 0) { red[wid * 2] = sv[0]; red[wid * 2 + 1] = sv[1]; }
    __syncthreads();
    #pragma unroll
    for (int r = 0; r < 2; ++r) {
        float v = red[r];
        #pragma unroll
        for (int w = 1; w < 8; ++w) v += red[w * 2 + r];
        sv[r] = v;
    }
    __syncthreads();
}

__global__ void __launch_bounds__(256)
softmax_kernel(const float* __restrict__ adj, float* __restrict__ out)
{
    // chunk remap: forward prefix for tail overlap, reversed bulk for L2 reuse
    const int cid = blockIdx.x;                       // 0..8191
    const int chunk = (cid < 2048) ? cid : (10239 - cid);
    const size_t row0 = (size_t)chunk * 2;

    __shared__ float red[16];
    __shared__ int ready;
    const int tid = threadIdx.x;
    const int wid = tid >> 5;
    const int lid = tid & 31;

    // adj prefetch (independent of syrk) — in flight during the gate spin
    float4 av[2][2];
    #pragma unroll
    for (int r = 0; r < 2; ++r) {
        const float4* a4 = reinterpret_cast<const float4*>(
            adj + (row0 + r) * NDIM);
        av[r][0] = __ldcs(a4 + tid);
        av[r][1] = __ldcs(a4 + tid + 256);
    }

    // gate: wait until all 16 tiles of this (batch,row-block) are published
    {
        const int b  = (int)(row0 >> 11);          // 2048 rows per batch
        const int rb = (int)((row0 & 2047) >> 7);  // 128-row block
        if (tid == 0) {
            volatile int* c = &g_cnt[b * NT + rb];
            while (*c < NT) __nanosleep(128);
            ready = 1;
        }
        __syncthreads();
        (void)ready;
        __threadfence();   // acquire: order energy reads after counter
    }

    float4 ev[2][2];
    #pragma unroll
    for (int r = 0; r < 2; ++r) {
        const float4* e4 = reinterpret_cast<const float4*>(
            g_energy + (row0 + r) * NDIM);
        ev[r][0] = __ldcs(e4 + tid);
        ev[r][1] = __ldcs(e4 + tid + 256);
    }

    float m1[2];
    #pragma unroll
    for (int r = 0; r < 2; ++r)
        m1[r] = fmaxf(fmaxf(fmaxf(ev[r][0].x, ev[r][0].y),
                            fmaxf(ev[r][0].z, ev[r][0].w)),
                      fmaxf(fmaxf(ev[r][1].x, ev[r][1].y),
                            fmaxf(ev[r][1].z, ev[r][1].w)));
    red2_max(m1, red, wid, lid);

    float t[2][8], m2[2];
    #pragma unroll
    for (int r = 0; r < 2; ++r) {
        t[r][0] = (m1[r] - ev[r][0].x) * av[r][0].x;
        t[r][1] = (m1[r] - ev[r][0].y) * av[r][0].y;
        t[r][2] = (m1[r] - ev[r][0].z) * av[r][0].z;
        t[r][3] = (m1[r] - ev[r][0].w) * av[r][0].w;
        t[r][4] = (m1[r] - ev[r][1].x) * av[r][1].x;
        t[r][5] = (m1[r] - ev[r][1].y) * av[r][1].y;
        t[r][6] = (m1[r] - ev[r][1].z) * av[r][1].z;
        t[r][7] = (m1[r] - ev[r][1].w) * av[r][1].w;
        float mm = t[r][0];
        #pragma unroll
        for (int i = 1; i < 8; ++i) mm = fmaxf(mm, t[r][i]);
        m2[r] = mm;
    }
    red2_max(m2, red, wid, lid);

    float sv[2];
    #pragma unroll
    for (int r = 0; r < 2; ++r) {
        float s = 0.0f;
        #pragma unroll
        for (int i = 0; i < 8; ++i) { t[r][i] = __expf(t[r][i] - m2[r]); s += t[r][i]; }
        sv[r] = s;
    }
    red2_sum(sv, red, wid, lid);

    #pragma unroll
    for (int r = 0; r < 2; ++r) {
        const float inv = 1.0f / sv[r];
        float4* o4 = reinterpret_cast<float4*>(out + (row0 + r) * NDIM);
        __stcs(o4 + tid, make_float4(t[r][0] * inv, t[r][1] * inv,
                                     t[r][2] * inv, t[r][3] * inv));
        __stcs(o4 + tid + 256, make_float4(t[r][4] * inv, t[r][5] * inv,
                                           t[r][6] * inv, t[r][7] * inv));
    }
}

// ---------------------------------------------------------------------------
extern "C" void kernel_launch(void* const* d_in, const int* in_sizes, int n_in,
                              void* d_out, int out_size)
{
    const float* h   = (const float*)d_in[0];   // [8, 2048, 256]
    const float* adj = (const float*)d_in[1];   // [8, 2048, 2048]
    float*       out = (float*)d_out;           // [8, 2048, 2048]
    (void)in_sizes; (void)n_in; (void)out_size;

    // Unconditional (no static guard). Host-side, idempotent, capture-safe.
    cudaFuncSetAttribute(syrk_mma_kernel,
                         cudaFuncAttributeMaxDynamicSharedMemorySize,
                         SYRK_SMEM);

    convert_kernel<<<2048, 256>>>(reinterpret_cast<const float4*>(h));

    // syrk with PSS: launches while convert finishes; griddepcontrol.wait
    // inside syrk provides the data dependency on convert.
    {
        cudaLaunchConfig_t cfg = {};
        cfg.gridDim  = dim3(NPAIR, BATCH);
        cfg.blockDim = dim3(256);
        cfg.dynamicSmemBytes = SYRK_SMEM;
        cfg.stream = 0;
        cudaLaunchAttribute attrs[1];
        attrs[0].id = cudaLaunchAttributeProgrammaticStreamSerialization;
        attrs[0].val.programmaticStreamSerializationAllowed = 1;
        cfg.attrs = attrs;
        cfg.numAttrs = 1;
        cudaLaunchKernelEx(&cfg, syrk_mma_kernel);
    }

    // softmax with PSS: launches during syrk's last wave; per-row-block
    // counter gates provide the data dependency.
    {
        cudaLaunchConfig_t cfg = {};
        cfg.gridDim  = dim3(BATCH * NDIM / 2);
        cfg.blockDim = dim3(256);
        cfg.dynamicSmemBytes = 0;
        cfg.stream = 0;
        cudaLaunchAttribute attrs[1];
        attrs[0].id = cudaLaunchAttributeProgrammaticStreamSerialization;
        attrs[0].val.programmaticStreamSerializationAllowed = 1;
        cfg.attrs = attrs;
        cfg.numAttrs = 1;
        cudaLaunchKernelEx(&cfg, softmax_kernel, adj, out);
    }
}

// round 15
// speedup vs baseline: 1.2346x; 1.0144x over previous
#include <cuda_runtime.h>
#include <cuda_bf16.h>
#include <cfloat>
#include <cstdint>

// Problem shape (fixed): B=8, N=2048, D=256
#define BATCH 8
#define NDIM  2048
#define DDIM  256

#define TILE 128
#define NT   (NDIM / TILE)               // 16
#define NPAIR ((NT * (NT + 1)) / 2)      // 136 upper-tri tile pairs

// ---------------------------------------------------------------------------
// Device scratch (allocation-free)
// ---------------------------------------------------------------------------
__device__ float g_energy[(size_t)BATCH * NDIM * NDIM];            // 134 MB
__device__ uint4 g_hhi[524288];   // h hi bf16
__device__ uint4 g_hlo[524288];   // h lo bf16
__device__ int   g_cnt[BATCH * NT];  // per (batch, tile-row) tiles done (goal 16)

// ---------------------------------------------------------------------------
// Kernel 0: split h -> hi/lo bf16; block 0 zeroes counters (every replay).
// Ends with PDL launch_dependents so syrk may begin launching.
// ---------------------------------------------------------------------------
__global__ void __launch_bounds__(256)
convert_kernel(const float4* __restrict__ h4)
{
    if (blockIdx.x == 0 && threadIdx.x < BATCH * NT)
        g_cnt[threadIdx.x] = 0;

    const int base = blockIdx.x * 512 + threadIdx.x;
    #pragma unroll
    for (int i = 0; i < 2; ++i) {
        const int f = base + i * 256;
        const float4 v = h4[f];
        __nv_bfloat16 hx = __float2bfloat16_rn(v.x);
        __nv_bfloat16 hy = __float2bfloat16_rn(v.y);
        __nv_bfloat16 hz = __float2bfloat16_rn(v.z);
        __nv_bfloat16 hw = __float2bfloat16_rn(v.w);
        float lx = v.x - __bfloat162float(hx);
        float ly = v.y - __bfloat162float(hy);
        float lz = v.z - __bfloat162float(hz);
        float lw = v.w - __bfloat162float(hw);
        __nv_bfloat162 hi01 = __nv_bfloat162(hx, hy);
        __nv_bfloat162 hi23 = __nv_bfloat162(hz, hw);
        __nv_bfloat162 lo01 = __floats2bfloat162_rn(lx, ly);
        __nv_bfloat162 lo23 = __floats2bfloat162_rn(lz, lw);
        uint2 uh, ul;
        uh.x = *reinterpret_cast<uint32_t*>(&hi01);
        uh.y = *reinterpret_cast<uint32_t*>(&hi23);
        ul.x = *reinterpret_cast<uint32_t*>(&lo01);
        ul.y = *reinterpret_cast<uint32_t*>(&lo23);
        reinterpret_cast<uint2*>(g_hhi)[f] = uh;
        reinterpret_cast<uint2*>(g_hlo)[f] = ul;
    }

    asm volatile("griddepcontrol.launch_dependents;" ::: "memory");
}

// ---------------------------------------------------------------------------
// mma.sync / ldmatrix / cp.async helpers (compute_100-safe)
// ---------------------------------------------------------------------------
__device__ __forceinline__ uint32_t smem_u32(const void* p) {
    uint32_t a;
    asm("{ .reg .u64 t; cvta.to.shared.u64 t, %1; cvt.u32.u64 %0, t; }"
        : "=r"(a) : "l"(p));
    return a;
}

__device__ __forceinline__ void ldsm_x4(uint32_t* r, uint32_t addr) {
    asm volatile("ldmatrix.sync.aligned.m8n8.x4.shared.b16 {%0,%1,%2,%3}, [%4];"
                 : "=r"(r[0]), "=r"(r[1]), "=r"(r[2]), "=r"(r[3]) : "r"(addr));
}

__device__ __forceinline__ void mma16816(float* d, const uint32_t* a,
                                         const uint32_t* b) {
    asm volatile("mma.sync.aligned.m16n8k16.row.col.f32.bf16.bf16.f32 "
                 "{%0,%1,%2,%3}, {%4,%5,%6,%7}, {%8,%9}, {%0,%1,%2,%3};"
                 : "+f"(d[0]), "+f"(d[1]), "+f"(d[2]), "+f"(d[3])
                 : "r"(a[0]), "r"(a[1]), "r"(a[2]), "r"(a[3]),
                   "r"(b[0]), "r"(b[1]));
}

__device__ __forceinline__ void cp_async16(uint32_t smem_dst, const void* gptr) {
    asm volatile("cp.async.cg.shared.global [%0], [%1], 16;\n"
                 :: "r"(smem_dst), "l"(__cvta_generic_to_global(gptr))
                 : "memory");
}
#define CP_COMMIT() asm volatile("cp.async.commit_group;\n" ::: "memory")
#define CP_WAIT(n)  asm volatile("cp.async.wait_group %0;\n" :: "n"(n) : "memory")

__device__ __forceinline__ uint32_t swz(int row, int kc) {
    return (uint32_t)(row * 64 + ((kc ^ ((row >> 1) & 3)) << 4));
}

// ---------------------------------------------------------------------------
// Kernel 1: SYRK energy[b] = h[b]*h[b]^T via split-bf16 3-MMA (mma.sync).
// R14 structure. Energy tiles written with DEFAULT-policy stores so the most
// recently produced tiles survive in L2 for the reversed-order softmax.
// ---------------------------------------------------------------------------
#define STAGE_BYTES 32768           // 4 arrays x 128 rows x 64B
#define ARR_BYTES   8192
#define SYRK_SMEM   (3 * STAGE_BYTES)   // 98304 >= epilogue 128*129*4=66048

__device__ __forceinline__ void load_stage(uint32_t sm_stage, int a_row0,
                                           int b_row0, int c, int tid,
                                           int batch4)
{
    #pragma unroll
    for (int i = 0; i < 8; ++i) {
        const int id  = tid + i * 256;      // 0..2047
        const int arr = id >> 9;            // 0=Ahi 1=Alo 2=Bhi 3=Blo
        const int cid = id & 511;
        const int row = cid >> 2;
        const int ch  = cid & 3;
        const uint32_t dst = sm_stage + arr * ARR_BYTES + swz(row, ch);
        const int grow = ((arr < 2) ? a_row0 : b_row0) + row;
        const uint4* src = ((arr & 1) ? g_hlo : g_hhi)
                           + batch4 + grow * 32 + c * 4 + ch;
        cp_async16(dst, src);
    }
}

__global__ void __launch_bounds__(256, 2)
syrk_mma_kernel()
{
    // PDL: wait for convert's data (and counter zeroing), then release the
    // softmax launch. Order is load-bearing.
    asm volatile("griddepcontrol.wait;" ::: "memory");
    asm volatile("griddepcontrol.launch_dependents;" ::: "memory");

    extern __shared__ char smc[];
    const uint32_t smem_base = smem_u32(smc);
    const int tid  = threadIdx.x;
    const int wid  = tid >> 5;
    const int lane = tid & 31;
    const int b    = blockIdx.y;

    // decode (ti, tj), ti <= tj
    int p = blockIdx.x;
    int ti = 0;
    while (p >= (NT - ti)) { p -= (NT - ti); ++ti; }
    const int tj = ti + p;

    const int a_base = ti * TILE;
    const int b_base = tj * TILE;
    const int batch4 = b * 65536;           // uint4 offset of batch

    const int wm = (wid & 3) * 32;          // warp row origin in tile
    const int wn = (wid >> 2) * 64;         // warp col origin in tile

    float acc[2][8][4];
    #pragma unroll
    for (int mt = 0; mt < 2; ++mt)
        #pragma unroll
        for (int nt = 0; nt < 8; ++nt)
            #pragma unroll
            for (int q = 0; q < 4; ++q)
                acc[mt][nt][q] = 0.0f;

    // prime two stages (ring slots 0, 1)
    load_stage(smem_base,               a_base, b_base, 0, tid, batch4);
    CP_COMMIT();
    load_stage(smem_base + STAGE_BYTES, a_base, b_base, 1, tid, batch4);
    CP_COMMIT();

    // ldmatrix per-lane address components
    const int r8   = lane & 7;
    const int a_dr = (lane & 8);            // (grp&1)<<3
    const int a_dk = (lane >> 4);           // grp>>1
    const int b_dr = (lane & 16) >> 1;      // (grp>>1)<<3
    const int b_dk = (lane >> 3) & 1;       // grp&1

    #pragma unroll 1
    for (int c = 0; c < 8; ++c) {
        if (c < 7) { CP_WAIT(1); } else { CP_WAIT(0); }
        __syncthreads();            // the ONLY barrier per chunk

        const uint32_t sb  = smem_base + (uint32_t)(c % 3) * STAGE_BYTES;
        const uint32_t sAh = sb;
        const uint32_t sAl = sb + ARR_BYTES;
        const uint32_t sBh = sb + 2 * ARR_BYTES;
        const uint32_t sBl = sb + 3 * ARR_BYTES;

        // prefetch chunk c+2 into ring slot (c+2)%3 (disjoint, no WAR barrier)
        if (c + 2 < 8) {
            load_stage(smem_base + (uint32_t)((c + 2) % 3) * STAGE_BYTES,
                       a_base, b_base, c + 2, tid, batch4);
        }
        CP_COMMIT();

        #pragma unroll
        for (int ks = 0; ks < 2; ++ks) {
            uint32_t ahi[2][4], alo[2][4], bf[4][4];

            #pragma unroll
            for (int mt = 0; mt < 2; ++mt) {
                const int row = wm + mt * 16 + a_dr + r8;
                const int kc  = 2 * ks + a_dk;
                const uint32_t off = swz(row, kc);
                ldsm_x4(ahi[mt], sAh + off);
                ldsm_x4(alo[mt], sAl + off);
            }
            #pragma unroll
            for (int np = 0; np < 4; ++np) {
                const int row = wn + np * 16 + b_dr + r8;
                const int kc  = 2 * ks + b_dk;
                ldsm_x4(bf[np], sBh + swz(row, kc));
            }
            // PASS 1: hh
            #pragma unroll
            for (int mt = 0; mt < 2; ++mt)
                #pragma unroll
                for (int np = 0; np < 4; ++np) {
                    mma16816(acc[mt][2 * np],     ahi[mt], &bf[np][0]);
                    mma16816(acc[mt][2 * np + 1], ahi[mt], &bf[np][2]);
                }
            // PASS 2: lh
            #pragma unroll
            for (int mt = 0; mt < 2; ++mt)
                #pragma unroll
                for (int np = 0; np < 4; ++np) {
                    mma16816(acc[mt][2 * np],     alo[mt], &bf[np][0]);
                    mma16816(acc[mt][2 * np + 1], alo[mt], &bf[np][2]);
                }
            // reload B-lo over the same registers
            #pragma unroll
            for (int np = 0; np < 4; ++np) {
                const int row = wn + np * 16 + b_dr + r8;
                const int kc  = 2 * ks + b_dk;
                ldsm_x4(bf[np], sBl + swz(row, kc));
            }
            // PASS 3: hl
            #pragma unroll
            for (int mt = 0; mt < 2; ++mt)
                #pragma unroll
                for (int np = 0; np < 4; ++np) {
                    mma16816(acc[mt][2 * np],     ahi[mt], &bf[np][0]);
                    mma16816(acc[mt][2 * np + 1], ahi[mt], &bf[np][2]);
                }
        }
    }

    // all warps must finish reading stages before sD overwrites them
    __syncthreads();

    // ---------------- epilogue: acc -> sD[128][129] -> gmem ----------------
    float* sD = reinterpret_cast<float*>(smc);
    {
        const int rq = lane >> 2;           // 0..7
        const int cq = (lane & 3) * 2;
        #pragma unroll
        for (int mt = 0; mt < 2; ++mt) {
            const int r0 = wm + mt * 16 + rq;
            #pragma unroll
            for (int nt = 0; nt < 8; ++nt) {
                const int cc = wn + nt * 8 + cq;
                sD[r0 * 129 + cc]           = acc[mt][nt][0];
                sD[r0 * 129 + cc + 1]       = acc[mt][nt][1];
                sD[(r0 + 8) * 129 + cc]     = acc[mt][nt][2];
                sD[(r0 + 8) * 129 + cc + 1] = acc[mt][nt][3];
            }
        }
    }
    __syncthreads();

    float* eb = g_energy + (size_t)b * NDIM * NDIM;

    // direct tile: DEFAULT-policy stores (lines should linger in L2 for the
    // reversed-order softmax consumer; __stcs here would mark them
    // evict-first and defeat the harvest)
    #pragma unroll 4
    for (int i = 0; i < 16; ++i) {
        const int idx = tid + i * 256;
        const int r  = idx >> 5;
        const int c4 = (idx & 31) * 4;
        float4 v = make_float4(sD[r * 129 + c4 + 0], sD[r * 129 + c4 + 1],
                               sD[r * 129 + c4 + 2], sD[r * 129 + c4 + 3]);
        *reinterpret_cast<float4*>(
            &eb[(size_t)(a_base + r) * NDIM + b_base + c4]) = v;
    }

    // mirror tile (transpose through smem), skip diagonal — default stores
    if (ti != tj) {
        #pragma unroll 4
        for (int i = 0; i < 16; ++i) {
            const int idx = tid + i * 256;
            const int r2 = idx >> 5;
            const int c4 = (idx & 31) * 4;
            float4 v = make_float4(sD[(c4 + 0) * 129 + r2], sD[(c4 + 1) * 129 + r2],
                                   sD[(c4 + 2) * 129 + r2], sD[(c4 + 3) * 129 + r2]);
            *reinterpret_cast<float4*>(
                &eb[(size_t)(b_base + r2) * NDIM + a_base + c4]) = v;
        }
    }

    // publish: release (fence per thread, barrier, single-thread atomics)
    __threadfence();
    __syncthreads();
    if (tid == 0) {
        atomicAdd(&g_cnt[b * NT + ti], 1);
        if (ti != tj) atomicAdd(&g_cnt[b * NT + tj], 1);
    }
}

// ---------------------------------------------------------------------------
// Kernel 2: softmax, counter-gated, PDL-early-launched (R13/R14 version).
// ---------------------------------------------------------------------------
__device__ __forceinline__ void red2_max(float mv[2], float* red,
                                         int wid, int lid)
{
    #pragma unroll
    for (int r = 0; r < 2; ++r)
        #pragma unroll
        for (int o = 16; o > 0; o >>= 1)
            mv[r] = fmaxf(mv[r], __shfl_xor_sync(0xFFFFFFFFu, mv[r], o));
    if (lid == 0) { red[wid * 2] = mv[0]; red[wid * 2 + 1] = mv[1]; }
    __syncthreads();
    #pragma unroll
    for (int r = 0; r < 2; ++r) {
        float v = red[r];
        #pragma unroll
        for (int w = 1; w < 8; ++w) v = fmaxf(v, red[w * 2 + r]);
        mv[r] = v;
    }
    __syncthreads();
}

__device__ __forceinline__ void red2_sum(float sv[2], float* red,
                                         int wid, int lid)
{
    #pragma unroll
    for (int r = 0; r < 2; ++r)
        #pragma unroll
        for (int o = 16; o > 0; o >>= 1)
            sv[r] += __shfl_xor_sync(0xFFFFFFFFu, sv[r], o);
    if (lid == 0) { red[wid * 2] = sv[0]; red[wid * 2 + 1] = sv[1]; }
    __syncthreads();
    #pragma unroll
    for (int r = 0; r < 2; ++r) {
        float v = red[r];
        #pragma unroll
        for (int w = 1; w < 8; ++w) v += red[w * 2 + r];
        sv[r] = v;
    }
    __syncthreads();
}

__global__ void __launch_bounds__(256)
softmax_kernel(const float* __restrict__ adj, float* __restrict__ out)
{
    // chunk remap: forward prefix for tail overlap, reversed bulk for L2 reuse
    const int cid = blockIdx.x;                       // 0..8191
    const int chunk = (cid < 2048) ? cid : (10239 - cid);
    const size_t row0 = (size_t)chunk * 2;

    __shared__ float red[16];
    __shared__ int ready;
    const int tid = threadIdx.x;
    const int wid = tid >> 5;
    const int lid = tid & 31;

    // adj prefetch (independent of syrk) — in flight during the gate spin
    float4 av[2][2];
    #pragma unroll
    for (int r = 0; r < 2; ++r) {
        const float4* a4 = reinterpret_cast<const float4*>(
            adj + (row0 + r) * NDIM);
        av[r][0] = __ldcs(a4 + tid);
        av[r][1] = __ldcs(a4 + tid + 256);
    }

    // gate: wait until all 16 tiles of this (batch,row-block) are published
    {
        const int b  = (int)(row0 >> 11);          // 2048 rows per batch
        const int rb = (int)((row0 & 2047) >> 7);  // 128-row block
        if (tid == 0) {
            volatile int* c = &g_cnt[b * NT + rb];
            while (*c < NT) __nanosleep(128);
            ready = 1;
        }
        __syncthreads();
        (void)ready;
        __threadfence();   // acquire: order energy reads after counter
    }

    float4 ev[2][2];
    #pragma unroll
    for (int r = 0; r < 2; ++r) {
        const float4* e4 = reinterpret_cast<const float4*>(
            g_energy + (row0 + r) * NDIM);
        ev[r][0] = __ldcs(e4 + tid);          // read-once: evict after read
        ev[r][1] = __ldcs(e4 + tid + 256);
    }

    float m1[2];
    #pragma unroll
    for (int r = 0; r < 2; ++r)
        m1[r] = fmaxf(fmaxf(fmaxf(ev[r][0].x, ev[r][0].y),
                            fmaxf(ev[r][0].z, ev[r][0].w)),
                      fmaxf(fmaxf(ev[r][1].x, ev[r][1].y),
                            fmaxf(ev[r][1].z, ev[r][1].w)));
    red2_max(m1, red, wid, lid);

    float t[2][8], m2[2];
    #pragma unroll
    for (int r = 0; r < 2; ++r) {
        t[r][0] = (m1[r] - ev[r][0].x) * av[r][0].x;
        t[r][1] = (m1[r] - ev[r][0].y) * av[r][0].y;
        t[r][2] = (m1[r] - ev[r][0].z) * av[r][0].z;
        t[r][3] = (m1[r] - ev[r][0].w) * av[r][0].w;
        t[r][4] = (m1[r] - ev[r][1].x) * av[r][1].x;
        t[r][5] = (m1[r] - ev[r][1].y) * av[r][1].y;
        t[r][6] = (m1[r] - ev[r][1].z) * av[r][1].z;
        t[r][7] = (m1[r] - ev[r][1].w) * av[r][1].w;
        float mm = t[r][0];
        #pragma unroll
        for (int i = 1; i < 8; ++i) mm = fmaxf(mm, t[r][i]);
        m2[r] = mm;
    }
    red2_max(m2, red, wid, lid);

    float sv[2];
    #pragma unroll
    for (int r = 0; r < 2; ++r) {
        float s = 0.0f;
        #pragma unroll
        for (int i = 0; i < 8; ++i) { t[r][i] = __expf(t[r][i] - m2[r]); s += t[r][i]; }
        sv[r] = s;
    }
    red2_sum(sv, red, wid, lid);

    #pragma unroll
    for (int r = 0; r < 2; ++r) {
        const float inv = 1.0f / sv[r];
        float4* o4 = reinterpret_cast<float4*>(out + (row0 + r) * NDIM);
        __stcs(o4 + tid, make_float4(t[r][0] * inv, t[r][1] * inv,
                                     t[r][2] * inv, t[r][3] * inv));
        __stcs(o4 + tid + 256, make_float4(t[r][4] * inv, t[r][5] * inv,
                                           t[r][6] * inv, t[r][7] * inv));
    }
}

// ---------------------------------------------------------------------------
extern "C" void kernel_launch(void* const* d_in, const int* in_sizes, int n_in,
                              void* d_out, int out_size)
{
    const float* h   = (const float*)d_in[0];   // [8, 2048, 256]
    const float* adj = (const float*)d_in[1];   // [8, 2048, 2048]
    float*       out = (float*)d_out;           // [8, 2048, 2048]
    (void)in_sizes; (void)n_in; (void)out_size;

    // Unconditional (no static guard). Host-side, idempotent, capture-safe.
    cudaFuncSetAttribute(syrk_mma_kernel,
                         cudaFuncAttributeMaxDynamicSharedMemorySize,
                         SYRK_SMEM);

    convert_kernel<<<2048, 256>>>(reinterpret_cast<const float4*>(h));

    // syrk with PSS: launches while convert finishes; griddepcontrol.wait
    // inside syrk provides the data dependency on convert.
    {
        cudaLaunchConfig_t cfg = {};
        cfg.gridDim  = dim3(NPAIR, BATCH);
        cfg.blockDim = dim3(256);
        cfg.dynamicSmemBytes = SYRK_SMEM;
        cfg.stream = 0;
        cudaLaunchAttribute attrs[1];
        attrs[0].id = cudaLaunchAttributeProgrammaticStreamSerialization;
        attrs[0].val.programmaticStreamSerializationAllowed = 1;
        cfg.attrs = attrs;
        cfg.numAttrs = 1;
        cudaLaunchKernelEx(&cfg, syrk_mma_kernel);
    }

    // softmax with PSS: launches during syrk's last wave; per-row-block
    // counter gates provide the data dependency.
    {
        cudaLaunchConfig_t cfg = {};
        cfg.gridDim  = dim3(BATCH * NDIM / 2);
        cfg.blockDim = dim3(256);
        cfg.dynamicSmemBytes = 0;
        cfg.stream = 0;
        cudaLaunchAttribute attrs[1];
        attrs[0].id = cudaLaunchAttributeProgrammaticStreamSerialization;
        attrs[0].val.programmaticStreamSerializationAllowed = 1;
        cfg.attrs = attrs;
        cfg.numAttrs = 1;
        cudaLaunchKernelEx(&cfg, softmax_kernel, adj, out);
    }
}